// round 7
// baseline (speedup 1.0000x reference)
#include <cuda_runtime.h>
#include <cstdint>

#define NNODES 100000
#define NEDGES 625000
#define DIM 128

// ---- per-buffer smem layout; two buffers of 64KB ----
#define A_HI 0            // 128 rows x 128B, swizzled bf16 k-major
#define A_LO 16384
#define B_HI 32768        // 128 n-rows x 128B
#define B_LO 49152
#define BUFSZ 65536
#define SMEM_BYTES (2 * BUFSZ)

// ---- device scratch ----
__device__ float g_agg[(size_t)NNODES * DIM];
__device__ float g_deg[NNODES];
__device__ int g_src[NEDGES];
__device__ int g_tgt[NEDGES];
__device__ int g_is64;
__device__ uint32_t g_h_hi[(size_t)NNODES * 64];
__device__ uint32_t g_h_lo[(size_t)NNODES * 64];
__device__ uint32_t g_e_hi[(size_t)NEDGES * 64];
__device__ uint32_t g_e_lo[(size_t)NEDGES * 64];
__device__ uint32_t g_imgP_hi[4 * 4096], g_imgP_lo[4 * 4096];
__device__ uint32_t g_imgQ_hi[4 * 4096], g_imgQ_lo[4 * 4096];
__device__ uint32_t g_imgW_hi[6 * 4096], g_imgW_lo[6 * 4096];

// ================= helpers =================
__device__ __forceinline__ uint32_t smem_u32(const void* p) {
    uint32_t a;
    asm("{ .reg .u64 t; cvta.to.shared.u64 t, %1; cvt.u32.u64 %0, t; }" : "=r"(a) : "l"(p));
    return a;
}
__device__ __forceinline__ void cvt_pair(float x, float y, uint32_t& hi, uint32_t& lo) {
    asm("cvt.rn.bf16x2.f32 %0, %2, %1;" : "=r"(hi) : "f"(x), "f"(y));
    float fx = __uint_as_float(hi << 16);
    float fy = __uint_as_float(hi & 0xffff0000u);
    float rx = x - fx, ry = y - fy;
    asm("cvt.rn.bf16x2.f32 %0, %2, %1;" : "=r"(lo) : "f"(rx), "f"(ry));
}
__device__ __forceinline__ void ldsm_x4(uint32_t* r, uint32_t addr) {
    asm volatile("ldmatrix.sync.aligned.m8n8.x4.shared.b16 {%0,%1,%2,%3}, [%4];"
                 : "=r"(r[0]), "=r"(r[1]), "=r"(r[2]), "=r"(r[3]) : "r"(addr));
}
__device__ __forceinline__ void mma_bf16(float* d, const uint32_t* a, const uint32_t* b) {
    asm volatile(
        "mma.sync.aligned.m16n8k16.row.col.f32.bf16.bf16.f32 "
        "{%0,%1,%2,%3}, {%4,%5,%6,%7}, {%8,%9}, {%0,%1,%2,%3};"
        : "+f"(d[0]), "+f"(d[1]), "+f"(d[2]), "+f"(d[3])
        : "r"(a[0]), "r"(a[1]), "r"(a[2]), "r"(a[3]), "r"(b[0]), "r"(b[1]));
}
__device__ __forceinline__ void cpa16(uint32_t dst, const void* src) {
    asm volatile("cp.async.cg.shared.global [%0], [%1], 16;" :: "r"(dst), "l"(src));
}
__device__ __forceinline__ void cpa_commit() {
    asm volatile("cp.async.commit_group;" ::: "memory");
}
template <int N>
__device__ __forceinline__ void cpa_wait() {
    asm volatile("cp.async.wait_group %0;" :: "n"(N) : "memory");
}

// ================= prep kernels =================
__global__ void detect_idx(const void* ei) {
    if (threadIdx.x == 0 && blockIdx.x == 0) {
        const unsigned long long* p = (const unsigned long long*)ei;
        int is64 = 1;
        for (int i = 0; i < 64; ++i)
            if (p[i] >= (unsigned long long)NNODES) { is64 = 0; break; }
        g_is64 = is64;
    }
}
__global__ void decode_idx(const void* ei) {
    int i = blockIdx.x * blockDim.x + threadIdx.x;
    size_t stride = (size_t)gridDim.x * blockDim.x;
    for (size_t j = i; j < (size_t)NNODES * DIM; j += stride) g_agg[j] = 0.f;
    for (size_t j = i; j < NNODES; j += stride) g_deg[j] = 0.f;
    if (i < NEDGES) {
        long long s, t;
        if (g_is64) { s = ((const long long*)ei)[i]; t = ((const long long*)ei)[NEDGES + i]; }
        else        { s = ((const int*)ei)[i];       t = ((const int*)ei)[NEDGES + i]; }
        if (s < 0) s = 0; if (s >= NNODES) s = NNODES - 1;
        if (t < 0) t = 0; if (t >= NNODES) t = NNODES - 1;
        g_src[i] = (int)s; g_tgt[i] = (int)t;
    }
}
__global__ void count_deg() {
    int i = blockIdx.x * blockDim.x + threadIdx.x;
    if (i < NEDGES) atomicAdd(&g_deg[g_tgt[i]], 1.f);
}
__global__ void prep_h(const float* __restrict__ h) {
    size_t id = (size_t)blockIdx.x * blockDim.x + threadIdx.x;
    if (id >= (size_t)NNODES * 32) return;
    float4 v = ((const float4*)h)[id];
    uint32_t h0, l0, h1, l1;
    cvt_pair(v.x, v.y, h0, l0);
    cvt_pair(v.z, v.w, h1, l1);
    ((uint2*)g_h_hi)[id] = make_uint2(h0, h1);
    ((uint2*)g_h_lo)[id] = make_uint2(l0, l1);
}
__global__ void prep_e(const float* __restrict__ e) {
    size_t id = (size_t)blockIdx.x * blockDim.x + threadIdx.x;
    if (id >= (size_t)NEDGES * 32) return;
    float4 v = ((const float4*)e)[id];
    uint32_t h0, l0, h1, l1;
    cvt_pair(v.x, v.y, h0, l0);
    cvt_pair(v.z, v.w, h1, l1);
    ((uint2*)g_e_hi)[id] = make_uint2(h0, h1);
    ((uint2*)g_e_lo)[id] = make_uint2(l0, l1);
}
__global__ void prep_w(const float* __restrict__ src, int sel, int nchunks) {
    int id = blockIdx.x * blockDim.x + threadIdx.x;
    if (id >= nchunks * 4096) return;
    uint32_t* dst_hi = (sel == 0) ? g_imgP_hi : (sel == 1) ? g_imgQ_hi : g_imgW_hi;
    uint32_t* dst_lo = (sel == 0) ? g_imgP_lo : (sel == 1) ? g_imgQ_lo : g_imgW_lo;
    int c = id >> 12, pos = id & 4095;
    int n = pos >> 5, kp = pos & 31;
    uint32_t off = n * 128 + kp * 4;
    uint32_t swz = off ^ ((off >> 3) & 0x70);
    int k0 = c * 64 + kp * 2;
    float x = src[(size_t)k0 * DIM + n];
    float y = src[(size_t)(k0 + 1) * DIM + n];
    uint32_t hi, lo;
    cvt_pair(x, y, hi, lo);
    dst_hi[(c << 12) + (swz >> 2)] = hi;
    dst_lo[(c << 12) + (swz >> 2)] = lo;
}

// ================= fills (cp.async) =================
// A: 128 rows; 2 threads/row (frow=tid>>1, fhalf=tid&1), 4x16B hi + 4x16B lo each
__device__ __forceinline__ void fill_a_async(uint32_t buf, int row, int half,
                                             const uint32_t* hi_src, const uint32_t* lo_src) {
    const uint32_t mask = (uint32_t)((row & 7) << 4);
    const uint32_t rowbase = buf + A_HI + (uint32_t)(row * 128);
#pragma unroll
    for (int i = 0; i < 4; ++i) {
        uint32_t off = (((uint32_t)((half * 4 + i) * 16)) ^ mask);
        cpa16(rowbase + off, hi_src + i * 4);
        cpa16(rowbase + 16384 + off, lo_src + i * 4);
    }
}
// register-path fill (k_node agg chunks): scale + split + STS
__device__ __forceinline__ void fill_a_f32(char* smem, uint32_t bufofs, int row, int half,
                                           const float* src, float sc) {
    const float4* s = (const float4*)src + half * 8;
    const uint32_t mask = (uint32_t)((row & 7) << 4);
#pragma unroll
    for (int i = 0; i < 4; ++i) {
        float4 a = s[2 * i], b = s[2 * i + 1];
        a.x *= sc; a.y *= sc; a.z *= sc; a.w *= sc;
        b.x *= sc; b.y *= sc; b.z *= sc; b.w *= sc;
        uint32_t h0, l0, h1, l1, h2, l2, h3, l3;
        cvt_pair(a.x, a.y, h0, l0); cvt_pair(a.z, a.w, h1, l1);
        cvt_pair(b.x, b.y, h2, l2); cvt_pair(b.z, b.w, h3, l3);
        uint32_t off = (uint32_t)(row * 128) + (((uint32_t)((half * 4 + i) * 16)) ^ mask);
        *(uint4*)(smem + bufofs + A_HI + off) = make_uint4(h0, h1, h2, h3);
        *(uint4*)(smem + bufofs + A_LO + off) = make_uint4(l0, l1, l2, l3);
    }
}
// B: 16KB hi + 16KB lo; 256 threads x (4+4) x 16B
__device__ __forceinline__ void fill_b_async(uint32_t buf, const uint32_t* ih,
                                             const uint32_t* il, int ch, int tid) {
    const uint32_t* sh = ih + ((size_t)ch << 12) + tid * 4;
    const uint32_t* sl = il + ((size_t)ch << 12) + tid * 4;
#pragma unroll
    for (int i = 0; i < 4; ++i) {
        cpa16(buf + B_HI + (uint32_t)((i * 256 + tid) * 16), sh + i * 1024);
        cpa16(buf + B_LO + (uint32_t)((i * 256 + tid) * 16), sl + i * 1024);
    }
}

// ================= compute =================
// Warp w: mh = w>>2 (64-row half), ws = w&3 (32-col slice). d[mf][nfl][4].
struct Frag {
    uint32_t aOff, aMask, aC0;
    uint32_t bOff, bMask, bC0;
};
__device__ __forceinline__ Frag make_frag(int warp, int lane) {
    Frag f;
    const int mh = warp >> 2, ws = warp & 3;
    f.aOff = A_HI + (uint32_t)((mh * 64 + (lane & 15)) * 128);
    f.aMask = (uint32_t)((lane & 7) << 4);
    f.aC0 = (uint32_t)(lane >> 4);
    f.bOff = B_HI + (uint32_t)(ws * 4096 + (lane & 7) * 128 + ((lane >> 4) & 1) * 1024);
    f.bMask = (uint32_t)((lane & 7) << 4);
    f.bC0 = (uint32_t)((lane >> 3) & 1);
    return f;
}
__device__ __forceinline__ void compute_chunk(uint32_t buf, const Frag& f, float (*d)[4][4]) {
#pragma unroll
    for (int ks = 0; ks < 4; ++ks) {
        const uint32_t aoff = (((f.aC0 + 2 * ks) * 16) ^ f.aMask);
        uint32_t ah[4][4], al[4][4];
#pragma unroll
        for (int mf = 0; mf < 4; ++mf) {
            ldsm_x4(ah[mf], buf + f.aOff + mf * 2048 + aoff);
            ldsm_x4(al[mf], buf + f.aOff + 16384 + mf * 2048 + aoff);
        }
        const uint32_t boff = (((f.bC0 + 2 * ks) * 16) ^ f.bMask);
#pragma unroll
        for (int p = 0; p < 2; ++p) {
            uint32_t bh[4], bl[4];
            ldsm_x4(bh, buf + f.bOff + p * 2048 + boff);
            ldsm_x4(bl, buf + f.bOff + 16384 + p * 2048 + boff);
            // pass-major order: same accumulator reused only every 8 MMAs
#pragma unroll
            for (int sub = 0; sub < 2; ++sub)
#pragma unroll
                for (int mf = 0; mf < 4; ++mf)
                    mma_bf16(d[mf][p * 2 + sub], ah[mf], bh + 2 * sub);
#pragma unroll
            for (int sub = 0; sub < 2; ++sub)
#pragma unroll
                for (int mf = 0; mf < 4; ++mf)
                    mma_bf16(d[mf][p * 2 + sub], ah[mf], bl + 2 * sub);
#pragma unroll
            for (int sub = 0; sub < 2; ++sub)
#pragma unroll
                for (int mf = 0; mf < 4; ++mf)
                    mma_bf16(d[mf][p * 2 + sub], al[mf], bh + 2 * sub);
        }
    }
}

// ================= GEMM kernels =================
// K1: messages = relu([h_u, e] @ P + pb) -> atomic scatter-add into g_agg
__global__ __launch_bounds__(256, 1) void k_msg(const float* __restrict__ Pb) {
    extern __shared__ char smem[];
    const uint32_t sb = smem_u32(smem);
    const int tid = threadIdx.x, lane = tid & 31, warp = tid >> 5;
    const int e0 = blockIdx.x * 128;
    const int frow = tid >> 1, fhalf = tid & 1;
    const int feg = e0 + frow;
    const int fegc = (feg < NEDGES) ? feg : (NEDGES - 1);
    const int fsrc = g_src[fegc];
    const Frag f = make_frag(warp, lane);

    float d[4][4][4];
#pragma unroll
    for (int i = 0; i < 4; ++i)
#pragma unroll
        for (int j = 0; j < 4; ++j)
#pragma unroll
            for (int k = 0; k < 4; ++k) d[i][j][k] = 0.f;

    // chunk sources: 0,1 = h_u; 2,3 = e
    const uint32_t* ahs[4] = {g_h_hi + (size_t)fsrc * 64 + fhalf * 16,
                              g_h_hi + (size_t)fsrc * 64 + 32 + fhalf * 16,
                              g_e_hi + (size_t)fegc * 64 + fhalf * 16,
                              g_e_hi + (size_t)fegc * 64 + 32 + fhalf * 16};
    const uint32_t* als[4] = {g_h_lo + (size_t)fsrc * 64 + fhalf * 16,
                              g_h_lo + (size_t)fsrc * 64 + 32 + fhalf * 16,
                              g_e_lo + (size_t)fegc * 64 + fhalf * 16,
                              g_e_lo + (size_t)fegc * 64 + 32 + fhalf * 16};

    fill_a_async(sb, frow, fhalf, ahs[0], als[0]);
    fill_b_async(sb, g_imgP_hi, g_imgP_lo, 0, tid);
    cpa_commit();
#pragma unroll 1
    for (int ch = 0; ch < 4; ++ch) {
        const uint32_t buf = sb + (ch & 1) * BUFSZ;
        if (ch + 1 < 4) {
            const uint32_t nbuf = sb + ((ch + 1) & 1) * BUFSZ;
            fill_a_async(nbuf, frow, fhalf, ahs[ch + 1], als[ch + 1]);
            fill_b_async(nbuf, g_imgP_hi, g_imgP_lo, ch + 1, tid);
            cpa_commit();
            cpa_wait<1>();
        } else {
            cpa_wait<0>();
        }
        __syncthreads();
        compute_chunk(buf, f, d);
        __syncthreads();
    }

    const int mh = warp >> 2, ws = warp & 3;
    const int r4 = lane >> 2, c2 = (lane & 3) * 2;
#pragma unroll
    for (int mf = 0; mf < 4; ++mf) {
#pragma unroll
        for (int half = 0; half < 2; ++half) {
            const int eg = e0 + mh * 64 + mf * 16 + r4 + half * 8;
            if (eg < NEDGES) {
                float* arow = g_agg + (size_t)__ldg(&g_tgt[eg]) * DIM;
#pragma unroll
                for (int nfl = 0; nfl < 4; ++nfl) {
                    const int col = ws * 32 + nfl * 8 + c2;
                    float2 bias = __ldg((const float2*)(Pb + col));
                    float2 v;
                    v.x = fmaxf(d[mf][nfl][half * 2 + 0] + bias.x, 0.f);
                    v.y = fmaxf(d[mf][nfl][half * 2 + 1] + bias.y, 0.f);
                    atomicAdd((float2*)(arow + col), v);
                }
            }
        }
    }
}

// K2: e_new = relu([e, h_u, h_v] @ W + wb)
__global__ __launch_bounds__(256, 1) void k_upd(const float* __restrict__ Wb,
                                                float* __restrict__ oute) {
    extern __shared__ char smem[];
    const uint32_t sb = smem_u32(smem);
    const int tid = threadIdx.x, lane = tid & 31, warp = tid >> 5;
    const int e0 = blockIdx.x * 128;
    const int frow = tid >> 1, fhalf = tid & 1;
    const int feg = e0 + frow;
    const int fegc = (feg < NEDGES) ? feg : (NEDGES - 1);
    const int fsrc = g_src[fegc];
    const int ftgt = g_tgt[fegc];
    const Frag f = make_frag(warp, lane);

    float d[4][4][4];
#pragma unroll
    for (int i = 0; i < 4; ++i)
#pragma unroll
        for (int j = 0; j < 4; ++j)
#pragma unroll
            for (int k = 0; k < 4; ++k) d[i][j][k] = 0.f;

    // chunk sources: 0,1 = e; 2,3 = h_u; 4,5 = h_v
    const uint32_t* ahs[6] = {g_e_hi + (size_t)fegc * 64 + fhalf * 16,
                              g_e_hi + (size_t)fegc * 64 + 32 + fhalf * 16,
                              g_h_hi + (size_t)fsrc * 64 + fhalf * 16,
                              g_h_hi + (size_t)fsrc * 64 + 32 + fhalf * 16,
                              g_h_hi + (size_t)ftgt * 64 + fhalf * 16,
                              g_h_hi + (size_t)ftgt * 64 + 32 + fhalf * 16};
    const uint32_t* als[6] = {g_e_lo + (size_t)fegc * 64 + fhalf * 16,
                              g_e_lo + (size_t)fegc * 64 + 32 + fhalf * 16,
                              g_h_lo + (size_t)fsrc * 64 + fhalf * 16,
                              g_h_lo + (size_t)fsrc * 64 + 32 + fhalf * 16,
                              g_h_lo + (size_t)ftgt * 64 + fhalf * 16,
                              g_h_lo + (size_t)ftgt * 64 + 32 + fhalf * 16};

    fill_a_async(sb, frow, fhalf, ahs[0], als[0]);
    fill_b_async(sb, g_imgW_hi, g_imgW_lo, 0, tid);
    cpa_commit();
#pragma unroll 1
    for (int ch = 0; ch < 6; ++ch) {
        const uint32_t buf = sb + (ch & 1) * BUFSZ;
        if (ch + 1 < 6) {
            const uint32_t nbuf = sb + ((ch + 1) & 1) * BUFSZ;
            fill_a_async(nbuf, frow, fhalf, ahs[ch + 1], als[ch + 1]);
            fill_b_async(nbuf, g_imgW_hi, g_imgW_lo, ch + 1, tid);
            cpa_commit();
            cpa_wait<1>();
        } else {
            cpa_wait<0>();
        }
        __syncthreads();
        compute_chunk(buf, f, d);
        __syncthreads();
    }

    const int mh = warp >> 2, ws = warp & 3;
    const int r4 = lane >> 2, c2 = (lane & 3) * 2;
#pragma unroll
    for (int mf = 0; mf < 4; ++mf) {
#pragma unroll
        for (int half = 0; half < 2; ++half) {
            const int eg = e0 + mh * 64 + mf * 16 + r4 + half * 8;
            if (eg < NEDGES) {
                float* orow = oute + (size_t)eg * DIM;
#pragma unroll
                for (int nfl = 0; nfl < 4; ++nfl) {
                    const int col = ws * 32 + nfl * 8 + c2;
                    float2 bias = __ldg((const float2*)(Wb + col));
                    float2 v;
                    v.x = fmaxf(d[mf][nfl][half * 2 + 0] + bias.x, 0.f);
                    v.y = fmaxf(d[mf][nfl][half * 2 + 1] + bias.y, 0.f);
                    *(float2*)(orow + col) = v;
                }
            }
        }
    }
}

// K3: h_new = relu([h, agg/deg] @ Q + qb)
__global__ __launch_bounds__(256, 1) void k_node(const float* __restrict__ Qb,
                                                 float* __restrict__ outh) {
    extern __shared__ char smem[];
    const uint32_t sb = smem_u32(smem);
    const int tid = threadIdx.x, lane = tid & 31, warp = tid >> 5;
    const int n0 = blockIdx.x * 128;
    const int frow = tid >> 1, fhalf = tid & 1;
    const int fng = n0 + frow;
    const int fnode = (fng < NNODES) ? fng : (NNODES - 1);
    const float finvd = 1.f / fmaxf(g_deg[fnode], 1.f);
    const Frag f = make_frag(warp, lane);

    float d[4][4][4];
#pragma unroll
    for (int i = 0; i < 4; ++i)
#pragma unroll
        for (int j = 0; j < 4; ++j)
#pragma unroll
            for (int k = 0; k < 4; ++k) d[i][j][k] = 0.f;

    const uint32_t* ahs[2] = {g_h_hi + (size_t)fnode * 64 + fhalf * 16,
                              g_h_hi + (size_t)fnode * 64 + 32 + fhalf * 16};
    const uint32_t* als[2] = {g_h_lo + (size_t)fnode * 64 + fhalf * 16,
                              g_h_lo + (size_t)fnode * 64 + 32 + fhalf * 16};

    // chunks: 0,1 = h (async); 2,3 = agg*invdeg (register path)
    fill_a_async(sb, frow, fhalf, ahs[0], als[0]);
    fill_b_async(sb, g_imgQ_hi, g_imgQ_lo, 0, tid);
    cpa_commit();
#pragma unroll 1
    for (int ch = 0; ch < 4; ++ch) {
        const uint32_t buf = sb + (ch & 1) * BUFSZ;
        if (ch + 1 < 4) {
            const uint32_t nbuf = sb + ((ch + 1) & 1) * BUFSZ;
            const uint32_t nofs = ((ch + 1) & 1) * BUFSZ;
            if (ch + 1 < 2) fill_a_async(nbuf, frow, fhalf, ahs[ch + 1], als[ch + 1]);
            else fill_a_f32(smem, nofs, frow, fhalf,
                            g_agg + (size_t)fnode * DIM + (ch + 1 - 2) * 64, finvd);
            fill_b_async(nbuf, g_imgQ_hi, g_imgQ_lo, ch + 1, tid);
            cpa_commit();
            cpa_wait<1>();
        } else {
            cpa_wait<0>();
        }
        __syncthreads();
        compute_chunk(buf, f, d);
        __syncthreads();
    }

    const int mh = warp >> 2, ws = warp & 3;
    const int r4 = lane >> 2, c2 = (lane & 3) * 2;
#pragma unroll
    for (int mf = 0; mf < 4; ++mf) {
#pragma unroll
        for (int half = 0; half < 2; ++half) {
            const int ng = n0 + mh * 64 + mf * 16 + r4 + half * 8;
            if (ng < NNODES) {
                float* orow = outh + (size_t)ng * DIM;
#pragma unroll
                for (int nfl = 0; nfl < 4; ++nfl) {
                    const int col = ws * 32 + nfl * 8 + c2;
                    float2 bias = __ldg((const float2*)(Qb + col));
                    float2 v;
                    v.x = fmaxf(d[mf][nfl][half * 2 + 0] + bias.x, 0.f);
                    v.y = fmaxf(d[mf][nfl][half * 2 + 1] + bias.y, 0.f);
                    *(float2*)(orow + col) = v;
                }
            }
        }
    }
}

extern "C" void kernel_launch(void* const* d_in, const int* in_sizes, int n_in,
                              void* d_out, int out_size) {
    const float* h    = (const float*)d_in[0];
    const float* e    = (const float*)d_in[1];
    const void*  eidx = d_in[2];
    const float* Pw   = (const float*)d_in[3];
    const float* Pb   = (const float*)d_in[4];
    const float* Qw   = (const float*)d_in[5];
    const float* Qb   = (const float*)d_in[6];
    const float* Ww   = (const float*)d_in[7];
    const float* Wb   = (const float*)d_in[8];

    float* outh = (float*)d_out;
    float* oute = outh + (size_t)NNODES * DIM;

    cudaFuncSetAttribute(k_msg, cudaFuncAttributeMaxDynamicSharedMemorySize, SMEM_BYTES);
    cudaFuncSetAttribute(k_upd, cudaFuncAttributeMaxDynamicSharedMemorySize, SMEM_BYTES);
    cudaFuncSetAttribute(k_node, cudaFuncAttributeMaxDynamicSharedMemorySize, SMEM_BYTES);

    const int dblocks = (NEDGES + 255) / 256;
    const int eg = (NEDGES + 127) / 128;   // 4883
    const int ng = (NNODES + 127) / 128;   // 782

    detect_idx<<<1, 32>>>(eidx);
    decode_idx<<<dblocks, 256>>>(eidx);
    count_deg<<<dblocks, 256>>>();
    prep_h<<<(NNODES * 32 + 255) / 256, 256>>>(h);
    prep_e<<<(NEDGES * 32 + 255) / 256, 256>>>(e);
    prep_w<<<64, 256>>>(Pw, 0, 4);
    prep_w<<<64, 256>>>(Qw, 1, 4);
    prep_w<<<96, 256>>>(Ww, 2, 6);
    k_msg<<<eg, 256, SMEM_BYTES>>>(Pb);
    k_node<<<ng, 256, SMEM_BYTES>>>(Qb, outh);
    k_upd<<<eg, 256, SMEM_BYTES>>>(Wb, oute);
}

// round 8
// speedup vs baseline: 1.6801x; 1.6801x over previous
#include <cuda_runtime.h>
#include <cstdint>

#define NNODES 100000
#define NEDGES 625000
#define DIM 128

// ---- per-buffer smem layout; two buffers of 32KB ----
#define A_OFF 0           // 128 rows x 128B, swizzled fp16 k-major
#define B_OFF 16384       // 128 n-rows x 128B
#define BUFSZ 32768
#define SMEM_BYTES (2 * BUFSZ)

// ---- device scratch ----
__device__ float g_agg[(size_t)NNODES * DIM];
__device__ float g_deg[NNODES];
__device__ int g_src[NEDGES];
__device__ int g_tgt[NEDGES];
__device__ int g_is64;
__device__ uint32_t g_h16[(size_t)NNODES * 64];   // fp16x2-packed h rows
__device__ uint32_t g_e16[(size_t)NEDGES * 64];   // fp16x2-packed e rows
__device__ uint32_t g_imgP[4 * 4096];             // swizzled fp16 weight images
__device__ uint32_t g_imgQ[4 * 4096];
__device__ uint32_t g_imgW[6 * 4096];

// ================= helpers =================
__device__ __forceinline__ uint32_t smem_u32(const void* p) {
    uint32_t a;
    asm("{ .reg .u64 t; cvta.to.shared.u64 t, %1; cvt.u32.u64 %0, t; }" : "=r"(a) : "l"(p));
    return a;
}
// pack (x,y) -> fp16x2 word (x in low half)
__device__ __forceinline__ uint32_t cvt_f16x2(float x, float y) {
    uint32_t r;
    asm("cvt.rn.f16x2.f32 %0, %2, %1;" : "=r"(r) : "f"(x), "f"(y));
    return r;
}
__device__ __forceinline__ void ldsm_x4(uint32_t* r, uint32_t addr) {
    asm volatile("ldmatrix.sync.aligned.m8n8.x4.shared.b16 {%0,%1,%2,%3}, [%4];"
                 : "=r"(r[0]), "=r"(r[1]), "=r"(r[2]), "=r"(r[3]) : "r"(addr));
}
__device__ __forceinline__ void mma_f16(float* d, const uint32_t* a, const uint32_t* b) {
    asm volatile(
        "mma.sync.aligned.m16n8k16.row.col.f32.f16.f16.f32 "
        "{%0,%1,%2,%3}, {%4,%5,%6,%7}, {%8,%9}, {%0,%1,%2,%3};"
        : "+f"(d[0]), "+f"(d[1]), "+f"(d[2]), "+f"(d[3])
        : "r"(a[0]), "r"(a[1]), "r"(a[2]), "r"(a[3]), "r"(b[0]), "r"(b[1]));
}
__device__ __forceinline__ void cpa16(uint32_t dst, const void* src) {
    asm volatile("cp.async.cg.shared.global [%0], [%1], 16;" :: "r"(dst), "l"(src));
}
__device__ __forceinline__ void cpa_commit() {
    asm volatile("cp.async.commit_group;" ::: "memory");
}
template <int N>
__device__ __forceinline__ void cpa_wait() {
    asm volatile("cp.async.wait_group %0;" :: "n"(N) : "memory");
}

// ================= prep kernels =================
__global__ void detect_idx(const void* ei) {
    if (threadIdx.x == 0 && blockIdx.x == 0) {
        const unsigned long long* p = (const unsigned long long*)ei;
        int is64 = 1;
        for (int i = 0; i < 64; ++i)
            if (p[i] >= (unsigned long long)NNODES) { is64 = 0; break; }
        g_is64 = is64;
    }
}
__global__ void decode_idx(const void* ei) {
    int i = blockIdx.x * blockDim.x + threadIdx.x;
    size_t stride = (size_t)gridDim.x * blockDim.x;
    for (size_t j = i; j < (size_t)NNODES * DIM; j += stride) g_agg[j] = 0.f;
    for (size_t j = i; j < NNODES; j += stride) g_deg[j] = 0.f;
    if (i < NEDGES) {
        long long s, t;
        if (g_is64) { s = ((const long long*)ei)[i]; t = ((const long long*)ei)[NEDGES + i]; }
        else        { s = ((const int*)ei)[i];       t = ((const int*)ei)[NEDGES + i]; }
        if (s < 0) s = 0; if (s >= NNODES) s = NNODES - 1;
        if (t < 0) t = 0; if (t >= NNODES) t = NNODES - 1;
        g_src[i] = (int)s; g_tgt[i] = (int)t;
    }
}
__global__ void count_deg() {
    int i = blockIdx.x * blockDim.x + threadIdx.x;
    if (i < NEDGES) atomicAdd(&g_deg[g_tgt[i]], 1.f);
}
__global__ void prep_h(const float* __restrict__ h) {
    size_t id = (size_t)blockIdx.x * blockDim.x + threadIdx.x;
    if (id >= (size_t)NNODES * 32) return;
    float4 v = ((const float4*)h)[id];
    ((uint2*)g_h16)[id] = make_uint2(cvt_f16x2(v.x, v.y), cvt_f16x2(v.z, v.w));
}
__global__ void prep_e(const float* __restrict__ e) {
    size_t id = (size_t)blockIdx.x * blockDim.x + threadIdx.x;
    if (id >= (size_t)NEDGES * 32) return;
    float4 v = ((const float4*)e)[id];
    ((uint2*)g_e16)[id] = make_uint2(cvt_f16x2(v.x, v.y), cvt_f16x2(v.z, v.w));
}
// swizzled B images: per K=64 chunk, 128 n-rows x 128B (k-major), XOR swizzle
__global__ void prep_w(const float* __restrict__ src, int sel, int nchunks) {
    int id = blockIdx.x * blockDim.x + threadIdx.x;
    if (id >= nchunks * 4096) return;
    uint32_t* dst = (sel == 0) ? g_imgP : (sel == 1) ? g_imgQ : g_imgW;
    int c = id >> 12, pos = id & 4095;
    int n = pos >> 5, kp = pos & 31;
    uint32_t off = n * 128 + kp * 4;
    uint32_t swz = off ^ ((off >> 3) & 0x70);
    int k0 = c * 64 + kp * 2;
    float x = src[(size_t)k0 * DIM + n];
    float y = src[(size_t)(k0 + 1) * DIM + n];
    dst[(c << 12) + (swz >> 2)] = cvt_f16x2(x, y);
}

// ================= fills (cp.async) =================
// A: 128 rows; 2 threads/row (frow=tid>>1, fhalf=tid&1), 4x16B each
__device__ __forceinline__ void fill_a_async(uint32_t buf, int row, int half,
                                             const uint32_t* src) {
    const uint32_t mask = (uint32_t)((row & 7) << 4);
    const uint32_t rowbase = buf + A_OFF + (uint32_t)(row * 128);
#pragma unroll
    for (int i = 0; i < 4; ++i) {
        uint32_t off = (((uint32_t)((half * 4 + i) * 16)) ^ mask);
        cpa16(rowbase + off, src + i * 4);
    }
}
// register-path fill (k_node agg chunks): scale + cvt + STS; 32 floats per thread
__device__ __forceinline__ void fill_a_f32(char* smem, uint32_t bufofs, int row, int half,
                                           const float* src, float sc) {
    const float4* s = (const float4*)src + half * 8;
    const uint32_t mask = (uint32_t)((row & 7) << 4);
#pragma unroll
    for (int i = 0; i < 4; ++i) {
        float4 a = s[2 * i], b = s[2 * i + 1];
        uint4 w;
        w.x = cvt_f16x2(a.x * sc, a.y * sc);
        w.y = cvt_f16x2(a.z * sc, a.w * sc);
        w.z = cvt_f16x2(b.x * sc, b.y * sc);
        w.w = cvt_f16x2(b.z * sc, b.w * sc);
        uint32_t off = (uint32_t)(row * 128) + (((uint32_t)((half * 4 + i) * 16)) ^ mask);
        *(uint4*)(smem + bufofs + A_OFF + off) = w;
    }
}
// B: 16KB per chunk; 256 threads x 4 x 16B
__device__ __forceinline__ void fill_b_async(uint32_t buf, const uint32_t* img, int ch,
                                             int tid) {
    const uint32_t* s = img + ((size_t)ch << 12) + tid * 4;
#pragma unroll
    for (int i = 0; i < 4; ++i)
        cpa16(buf + B_OFF + (uint32_t)((i * 256 + tid) * 16), s + i * 1024);
}

// ================= compute =================
// Warp w: mh = w>>2 (64-row half), ws = w&3 (32-col slice). d[mf][nfl][4].
struct Frag {
    uint32_t aOff, aMask, aC0;
    uint32_t bOff, bMask, bC0;
};
__device__ __forceinline__ Frag make_frag(int warp, int lane) {
    Frag f;
    const int mh = warp >> 2, ws = warp & 3;
    f.aOff = A_OFF + (uint32_t)((mh * 64 + (lane & 15)) * 128);
    f.aMask = (uint32_t)((lane & 7) << 4);
    f.aC0 = (uint32_t)(lane >> 4);
    f.bOff = B_OFF + (uint32_t)(ws * 4096 + (lane & 7) * 128 + ((lane >> 4) & 1) * 1024);
    f.bMask = (uint32_t)((lane & 7) << 4);
    f.bC0 = (uint32_t)((lane >> 3) & 1);
    return f;
}
__device__ __forceinline__ void compute_chunk(uint32_t buf, const Frag& f, float (*d)[4][4]) {
#pragma unroll
    for (int ks = 0; ks < 4; ++ks) {
        const uint32_t aoff = (((f.aC0 + 2 * ks) * 16) ^ f.aMask);
        uint32_t a[4][4];
#pragma unroll
        for (int mf = 0; mf < 4; ++mf)
            ldsm_x4(a[mf], buf + f.aOff + mf * 2048 + aoff);
        const uint32_t boff = (((f.bC0 + 2 * ks) * 16) ^ f.bMask);
#pragma unroll
        for (int p = 0; p < 2; ++p) {
            uint32_t b[4];
            ldsm_x4(b, buf + f.bOff + p * 2048 + boff);
#pragma unroll
            for (int sub = 0; sub < 2; ++sub)
#pragma unroll
                for (int mf = 0; mf < 4; ++mf)
                    mma_f16(d[mf][p * 2 + sub], a[mf], b + 2 * sub);
        }
    }
}

// ================= GEMM kernels =================
// K1: messages = relu([h_u, e] @ P + pb) -> atomic scatter-add into g_agg
__global__ __launch_bounds__(256, 1) void k_msg(const float* __restrict__ Pb) {
    extern __shared__ char smem[];
    const uint32_t sb = smem_u32(smem);
    const int tid = threadIdx.x, lane = tid & 31, warp = tid >> 5;
    const int e0 = blockIdx.x * 128;
    const int frow = tid >> 1, fhalf = tid & 1;
    const int feg = e0 + frow;
    const int fegc = (feg < NEDGES) ? feg : (NEDGES - 1);
    const int fsrc = g_src[fegc];
    const Frag f = make_frag(warp, lane);

    float d[4][4][4];
#pragma unroll
    for (int i = 0; i < 4; ++i)
#pragma unroll
        for (int j = 0; j < 4; ++j)
#pragma unroll
            for (int k = 0; k < 4; ++k) d[i][j][k] = 0.f;

    // chunk sources: 0,1 = h_u; 2,3 = e
    const uint32_t* as[4] = {g_h16 + (size_t)fsrc * 64 + fhalf * 16,
                             g_h16 + (size_t)fsrc * 64 + 32 + fhalf * 16,
                             g_e16 + (size_t)fegc * 64 + fhalf * 16,
                             g_e16 + (size_t)fegc * 64 + 32 + fhalf * 16};

    fill_a_async(sb, frow, fhalf, as[0]);
    fill_b_async(sb, g_imgP, 0, tid);
    cpa_commit();
#pragma unroll 1
    for (int ch = 0; ch < 4; ++ch) {
        const uint32_t buf = sb + (ch & 1) * BUFSZ;
        if (ch + 1 < 4) {
            const uint32_t nbuf = sb + ((ch + 1) & 1) * BUFSZ;
            fill_a_async(nbuf, frow, fhalf, as[ch + 1]);
            fill_b_async(nbuf, g_imgP, ch + 1, tid);
            cpa_commit();
            cpa_wait<1>();
        } else {
            cpa_wait<0>();
        }
        __syncthreads();
        compute_chunk(buf, f, d);
        __syncthreads();
    }

    const int mh = warp >> 2, ws = warp & 3;
    const int r4 = lane >> 2, c2 = (lane & 3) * 2;
#pragma unroll
    for (int mf = 0; mf < 4; ++mf) {
#pragma unroll
        for (int half = 0; half < 2; ++half) {
            const int eg = e0 + mh * 64 + mf * 16 + r4 + half * 8;
            if (eg < NEDGES) {
                float* arow = g_agg + (size_t)__ldg(&g_tgt[eg]) * DIM;
#pragma unroll
                for (int nfl = 0; nfl < 4; ++nfl) {
                    const int col = ws * 32 + nfl * 8 + c2;
                    float2 bias = __ldg((const float2*)(Pb + col));
                    float2 v;
                    v.x = fmaxf(d[mf][nfl][half * 2 + 0] + bias.x, 0.f);
                    v.y = fmaxf(d[mf][nfl][half * 2 + 1] + bias.y, 0.f);
                    atomicAdd((float2*)(arow + col), v);
                }
            }
        }
    }
}

// K2: e_new = relu([e, h_u, h_v] @ W + wb)
__global__ __launch_bounds__(256, 1) void k_upd(const float* __restrict__ Wb,
                                                float* __restrict__ oute) {
    extern __shared__ char smem[];
    const uint32_t sb = smem_u32(smem);
    const int tid = threadIdx.x, lane = tid & 31, warp = tid >> 5;
    const int e0 = blockIdx.x * 128;
    const int frow = tid >> 1, fhalf = tid & 1;
    const int feg = e0 + frow;
    const int fegc = (feg < NEDGES) ? feg : (NEDGES - 1);
    const int fsrc = g_src[fegc];
    const int ftgt = g_tgt[fegc];
    const Frag f = make_frag(warp, lane);

    float d[4][4][4];
#pragma unroll
    for (int i = 0; i < 4; ++i)
#pragma unroll
        for (int j = 0; j < 4; ++j)
#pragma unroll
            for (int k = 0; k < 4; ++k) d[i][j][k] = 0.f;

    // chunk sources: 0,1 = e; 2,3 = h_u; 4,5 = h_v
    const uint32_t* as[6] = {g_e16 + (size_t)fegc * 64 + fhalf * 16,
                             g_e16 + (size_t)fegc * 64 + 32 + fhalf * 16,
                             g_h16 + (size_t)fsrc * 64 + fhalf * 16,
                             g_h16 + (size_t)fsrc * 64 + 32 + fhalf * 16,
                             g_h16 + (size_t)ftgt * 64 + fhalf * 16,
                             g_h16 + (size_t)ftgt * 64 + 32 + fhalf * 16};

    fill_a_async(sb, frow, fhalf, as[0]);
    fill_b_async(sb, g_imgW, 0, tid);
    cpa_commit();
#pragma unroll 1
    for (int ch = 0; ch < 6; ++ch) {
        const uint32_t buf = sb + (ch & 1) * BUFSZ;
        if (ch + 1 < 6) {
            const uint32_t nbuf = sb + ((ch + 1) & 1) * BUFSZ;
            fill_a_async(nbuf, frow, fhalf, as[ch + 1]);
            fill_b_async(nbuf, g_imgW, ch + 1, tid);
            cpa_commit();
            cpa_wait<1>();
        } else {
            cpa_wait<0>();
        }
        __syncthreads();
        compute_chunk(buf, f, d);
        __syncthreads();
    }

    const int mh = warp >> 2, ws = warp & 3;
    const int r4 = lane >> 2, c2 = (lane & 3) * 2;
#pragma unroll
    for (int mf = 0; mf < 4; ++mf) {
#pragma unroll
        for (int half = 0; half < 2; ++half) {
            const int eg = e0 + mh * 64 + mf * 16 + r4 + half * 8;
            if (eg < NEDGES) {
                float* orow = oute + (size_t)eg * DIM;
#pragma unroll
                for (int nfl = 0; nfl < 4; ++nfl) {
                    const int col = ws * 32 + nfl * 8 + c2;
                    float2 bias = __ldg((const float2*)(Wb + col));
                    float2 v;
                    v.x = fmaxf(d[mf][nfl][half * 2 + 0] + bias.x, 0.f);
                    v.y = fmaxf(d[mf][nfl][half * 2 + 1] + bias.y, 0.f);
                    *(float2*)(orow + col) = v;
                }
            }
        }
    }
}

// K3: h_new = relu([h, agg/deg] @ Q + qb)
__global__ __launch_bounds__(256, 1) void k_node(const float* __restrict__ Qb,
                                                 float* __restrict__ outh) {
    extern __shared__ char smem[];
    const uint32_t sb = smem_u32(smem);
    const int tid = threadIdx.x, lane = tid & 31, warp = tid >> 5;
    const int n0 = blockIdx.x * 128;
    const int frow = tid >> 1, fhalf = tid & 1;
    const int fng = n0 + frow;
    const int fnode = (fng < NNODES) ? fng : (NNODES - 1);
    const float finvd = 1.f / fmaxf(g_deg[fnode], 1.f);
    const Frag f = make_frag(warp, lane);

    float d[4][4][4];
#pragma unroll
    for (int i = 0; i < 4; ++i)
#pragma unroll
        for (int j = 0; j < 4; ++j)
#pragma unroll
            for (int k = 0; k < 4; ++k) d[i][j][k] = 0.f;

    const uint32_t* as[2] = {g_h16 + (size_t)fnode * 64 + fhalf * 16,
                             g_h16 + (size_t)fnode * 64 + 32 + fhalf * 16};

    // chunks: 0,1 = h (async); 2,3 = agg*invdeg (register path)
    fill_a_async(sb, frow, fhalf, as[0]);
    fill_b_async(sb, g_imgQ, 0, tid);
    cpa_commit();
#pragma unroll 1
    for (int ch = 0; ch < 4; ++ch) {
        const uint32_t buf = sb + (ch & 1) * BUFSZ;
        if (ch + 1 < 4) {
            const uint32_t nbuf = sb + ((ch + 1) & 1) * BUFSZ;
            const uint32_t nofs = ((ch + 1) & 1) * BUFSZ;
            if (ch + 1 < 2) fill_a_async(nbuf, frow, fhalf, as[ch + 1]);
            else fill_a_f32(smem, nofs, frow, fhalf,
                            g_agg + (size_t)fnode * DIM + (ch + 1 - 2) * 64, finvd);
            fill_b_async(nbuf, g_imgQ, ch + 1, tid);
            cpa_commit();
            cpa_wait<1>();
        } else {
            cpa_wait<0>();
        }
        __syncthreads();
        compute_chunk(buf, f, d);
        __syncthreads();
    }

    const int mh = warp >> 2, ws = warp & 3;
    const int r4 = lane >> 2, c2 = (lane & 3) * 2;
#pragma unroll
    for (int mf = 0; mf < 4; ++mf) {
#pragma unroll
        for (int half = 0; half < 2; ++half) {
            const int ng = n0 + mh * 64 + mf * 16 + r4 + half * 8;
            if (ng < NNODES) {
                float* orow = outh + (size_t)ng * DIM;
#pragma unroll
                for (int nfl = 0; nfl < 4; ++nfl) {
                    const int col = ws * 32 + nfl * 8 + c2;
                    float2 bias = __ldg((const float2*)(Qb + col));
                    float2 v;
                    v.x = fmaxf(d[mf][nfl][half * 2 + 0] + bias.x, 0.f);
                    v.y = fmaxf(d[mf][nfl][half * 2 + 1] + bias.y, 0.f);
                    *(float2*)(orow + col) = v;
                }
            }
        }
    }
}

extern "C" void kernel_launch(void* const* d_in, const int* in_sizes, int n_in,
                              void* d_out, int out_size) {
    const float* h    = (const float*)d_in[0];
    const float* e    = (const float*)d_in[1];
    const void*  eidx = d_in[2];
    const float* Pw   = (const float*)d_in[3];
    const float* Pb   = (const float*)d_in[4];
    const float* Qw   = (const float*)d_in[5];
    const float* Qb   = (const float*)d_in[6];
    const float* Ww   = (const float*)d_in[7];
    const float* Wb   = (const float*)d_in[8];

    float* outh = (float*)d_out;
    float* oute = outh + (size_t)NNODES * DIM;

    cudaFuncSetAttribute(k_msg, cudaFuncAttributeMaxDynamicSharedMemorySize, SMEM_BYTES);
    cudaFuncSetAttribute(k_upd, cudaFuncAttributeMaxDynamicSharedMemorySize, SMEM_BYTES);
    cudaFuncSetAttribute(k_node, cudaFuncAttributeMaxDynamicSharedMemorySize, SMEM_BYTES);

    const int dblocks = (NEDGES + 255) / 256;
    const int eg = (NEDGES + 127) / 128;   // 4883
    const int ng = (NNODES + 127) / 128;   // 782

    detect_idx<<<1, 32>>>(eidx);
    decode_idx<<<dblocks, 256>>>(eidx);
    count_deg<<<dblocks, 256>>>();
    prep_h<<<(NNODES * 32 + 255) / 256, 256>>>(h);
    prep_e<<<(NEDGES * 32 + 255) / 256, 256>>>(e);
    prep_w<<<64, 256>>>(Pw, 0, 4);
    prep_w<<<64, 256>>>(Qw, 1, 4);
    prep_w<<<96, 256>>>(Ww, 2, 6);
    k_msg<<<eg, 256, SMEM_BYTES>>>(Pb);
    k_node<<<ng, 256, SMEM_BYTES>>>(Qb, outh);
    k_upd<<<eg, 256, SMEM_BYTES>>>(Wb, oute);
}

// round 9
// speedup vs baseline: 1.9959x; 1.1879x over previous
#include <cuda_runtime.h>
#include <cstdint>

#define NNODES 100000
#define NEDGES 625000
#define DIM 128

// ---- per-buffer smem layout; two buffers of 48KB ----
#define A_OFF 0           // 128 rows x 128B, swizzled fp16 k-major
#define BP_OFF 16384      // P-weight chunk (128 n-rows x 128B)
#define BW_OFF 32768      // W-weight chunk
#define BUFSZ 49152
#define SMEM_BYTES (2 * BUFSZ)

// ---- device scratch ----
__device__ float g_agg[(size_t)NNODES * DIM];
__device__ float g_deg[NNODES];
__device__ int g_src[NEDGES];
__device__ int g_tgt[NEDGES];
__device__ int g_is64;
__device__ uint32_t g_h16[(size_t)NNODES * 64];   // fp16x2-packed h rows
__device__ uint32_t g_e16[(size_t)NEDGES * 64];   // fp16x2-packed e rows
__device__ uint32_t g_imgP[4 * 4096];             // swizzled fp16 weight images
__device__ uint32_t g_imgQ[4 * 4096];
__device__ uint32_t g_imgW[6 * 4096];

// ================= helpers =================
__device__ __forceinline__ uint32_t smem_u32(const void* p) {
    uint32_t a;
    asm("{ .reg .u64 t; cvta.to.shared.u64 t, %1; cvt.u32.u64 %0, t; }" : "=r"(a) : "l"(p));
    return a;
}
__device__ __forceinline__ uint32_t cvt_f16x2(float x, float y) {
    uint32_t r;
    asm("cvt.rn.f16x2.f32 %0, %2, %1;" : "=r"(r) : "f"(x), "f"(y));
    return r;
}
__device__ __forceinline__ void ldsm_x4(uint32_t* r, uint32_t addr) {
    asm volatile("ldmatrix.sync.aligned.m8n8.x4.shared.b16 {%0,%1,%2,%3}, [%4];"
                 : "=r"(r[0]), "=r"(r[1]), "=r"(r[2]), "=r"(r[3]) : "r"(addr));
}
__device__ __forceinline__ void mma_f16(float* d, const uint32_t* a, const uint32_t* b) {
    asm volatile(
        "mma.sync.aligned.m16n8k16.row.col.f32.f16.f16.f32 "
        "{%0,%1,%2,%3}, {%4,%5,%6,%7}, {%8,%9}, {%0,%1,%2,%3};"
        : "+f"(d[0]), "+f"(d[1]), "+f"(d[2]), "+f"(d[3])
        : "r"(a[0]), "r"(a[1]), "r"(a[2]), "r"(a[3]), "r"(b[0]), "r"(b[1]));
}
__device__ __forceinline__ void cpa16(uint32_t dst, const void* src) {
    asm volatile("cp.async.cg.shared.global [%0], [%1], 16;" :: "r"(dst), "l"(src));
}
__device__ __forceinline__ void cpa_commit() {
    asm volatile("cp.async.commit_group;" ::: "memory");
}
template <int N>
__device__ __forceinline__ void cpa_wait() {
    asm volatile("cp.async.wait_group %0;" :: "n"(N) : "memory");
}
__device__ __forceinline__ void red_v4(float* ptr, float a, float b, float c, float d) {
    asm volatile("red.global.v4.f32.add [%0], {%1, %2, %3, %4};"
                 :: "l"(ptr), "f"(a), "f"(b), "f"(c), "f"(d) : "memory");
}

// ================= prep kernels =================
__global__ void detect_idx(const void* ei) {
    if (threadIdx.x == 0 && blockIdx.x == 0) {
        const unsigned long long* p = (const unsigned long long*)ei;
        int is64 = 1;
        for (int i = 0; i < 64; ++i)
            if (p[i] >= (unsigned long long)NNODES) { is64 = 0; break; }
        g_is64 = is64;
    }
}
__global__ void decode_idx(const void* ei) {
    int i = blockIdx.x * blockDim.x + threadIdx.x;
    size_t stride = (size_t)gridDim.x * blockDim.x;
    for (size_t j = i; j < (size_t)NNODES * DIM; j += stride) g_agg[j] = 0.f;
    for (size_t j = i; j < NNODES; j += stride) g_deg[j] = 0.f;
    if (i < NEDGES) {
        long long s, t;
        if (g_is64) { s = ((const long long*)ei)[i]; t = ((const long long*)ei)[NEDGES + i]; }
        else        { s = ((const int*)ei)[i];       t = ((const int*)ei)[NEDGES + i]; }
        if (s < 0) s = 0; if (s >= NNODES) s = NNODES - 1;
        if (t < 0) t = 0; if (t >= NNODES) t = NNODES - 1;
        g_src[i] = (int)s; g_tgt[i] = (int)t;
    }
}
__global__ void count_deg() {
    int i = blockIdx.x * blockDim.x + threadIdx.x;
    if (i < NEDGES) atomicAdd(&g_deg[g_tgt[i]], 1.f);
}
__global__ void prep_h(const float* __restrict__ h) {
    size_t id = (size_t)blockIdx.x * blockDim.x + threadIdx.x;
    if (id >= (size_t)NNODES * 32) return;
    float4 v = ((const float4*)h)[id];
    ((uint2*)g_h16)[id] = make_uint2(cvt_f16x2(v.x, v.y), cvt_f16x2(v.z, v.w));
}
__global__ void prep_e(const float* __restrict__ e) {
    size_t id = (size_t)blockIdx.x * blockDim.x + threadIdx.x;
    if (id >= (size_t)NEDGES * 32) return;
    float4 v = ((const float4*)e)[id];
    ((uint2*)g_e16)[id] = make_uint2(cvt_f16x2(v.x, v.y), cvt_f16x2(v.z, v.w));
}
__global__ void prep_w(const float* __restrict__ src, int sel, int nchunks) {
    int id = blockIdx.x * blockDim.x + threadIdx.x;
    if (id >= nchunks * 4096) return;
    uint32_t* dst = (sel == 0) ? g_imgP : (sel == 1) ? g_imgQ : g_imgW;
    int c = id >> 12, pos = id & 4095;
    int n = pos >> 5, kp = pos & 31;
    uint32_t off = n * 128 + kp * 4;
    uint32_t swz = off ^ ((off >> 3) & 0x70);
    int k0 = c * 64 + kp * 2;
    float x = src[(size_t)k0 * DIM + n];
    float y = src[(size_t)(k0 + 1) * DIM + n];
    dst[(c << 12) + (swz >> 2)] = cvt_f16x2(x, y);
}

// ================= fills =================
__device__ __forceinline__ void fill_a_async(uint32_t buf, int row, int half,
                                             const uint32_t* src) {
    const uint32_t mask = (uint32_t)((row & 7) << 4);
    const uint32_t rowbase = buf + A_OFF + (uint32_t)(row * 128);
#pragma unroll
    for (int i = 0; i < 4; ++i) {
        uint32_t off = (((uint32_t)((half * 4 + i) * 16)) ^ mask);
        cpa16(rowbase + off, src + i * 4);
    }
}
__device__ __forceinline__ void fill_a_f32(char* smem, uint32_t bufofs, int row, int half,
                                           const float* src, float sc) {
    const float4* s = (const float4*)src + half * 8;
    const uint32_t mask = (uint32_t)((row & 7) << 4);
#pragma unroll
    for (int i = 0; i < 4; ++i) {
        float4 a = s[2 * i], b = s[2 * i + 1];
        uint4 w;
        w.x = cvt_f16x2(a.x * sc, a.y * sc);
        w.y = cvt_f16x2(a.z * sc, a.w * sc);
        w.z = cvt_f16x2(b.x * sc, b.y * sc);
        w.w = cvt_f16x2(b.z * sc, b.w * sc);
        uint32_t off = (uint32_t)(row * 128) + (((uint32_t)((half * 4 + i) * 16)) ^ mask);
        *(uint4*)(smem + bufofs + A_OFF + off) = w;
    }
}
__device__ __forceinline__ void fill_b_async(uint32_t buf, uint32_t area,
                                             const uint32_t* img, int ch, int tid) {
    const uint32_t* s = img + ((size_t)ch << 12) + tid * 4;
#pragma unroll
    for (int i = 0; i < 4; ++i)
        cpa16(buf + area + (uint32_t)((i * 256 + tid) * 16), s + i * 1024);
}

// ================= compute =================
struct Frag {
    uint32_t aOff, aMask, aC0;
    uint32_t bRel, bMask, bC0;
};
__device__ __forceinline__ Frag make_frag(int warp, int lane) {
    Frag f;
    const int mh = warp >> 2, ws = warp & 3;
    f.aOff = A_OFF + (uint32_t)((mh * 64 + (lane & 15)) * 128);
    f.aMask = (uint32_t)((lane & 7) << 4);
    f.aC0 = (uint32_t)(lane >> 4);
    f.bRel = (uint32_t)(ws * 4096 + (lane & 7) * 128 + ((lane >> 4) & 1) * 1024);
    f.bMask = (uint32_t)((lane & 7) << 4);
    f.bC0 = (uint32_t)((lane >> 3) & 1);
    return f;
}
// one K=64 chunk into dW (always) and dP (if hasP)
__device__ __forceinline__ void compute_chunk_dual(uint32_t buf, const Frag& f,
                                                   float (*dW)[4][4], float (*dP)[4][4],
                                                   bool hasP) {
#pragma unroll
    for (int ks = 0; ks < 4; ++ks) {
        const uint32_t aoff = (((f.aC0 + 2 * ks) * 16) ^ f.aMask);
        uint32_t a[4][4];
#pragma unroll
        for (int mf = 0; mf < 4; ++mf)
            ldsm_x4(a[mf], buf + f.aOff + mf * 2048 + aoff);
        const uint32_t boff = f.bRel + (((f.bC0 + 2 * ks) * 16) ^ f.bMask);
#pragma unroll
        for (int p = 0; p < 2; ++p) {
            uint32_t b[4];
            ldsm_x4(b, buf + BW_OFF + p * 2048 + boff);
#pragma unroll
            for (int sub = 0; sub < 2; ++sub)
#pragma unroll
                for (int mf = 0; mf < 4; ++mf)
                    mma_f16(dW[mf][p * 2 + sub], a[mf], b + 2 * sub);
            if (hasP) {
                uint32_t bp[4];
                ldsm_x4(bp, buf + BP_OFF + p * 2048 + boff);
#pragma unroll
                for (int sub = 0; sub < 2; ++sub)
#pragma unroll
                    for (int mf = 0; mf < 4; ++mf)
                        mma_f16(dP[mf][p * 2 + sub], a[mf], bp + 2 * sub);
            }
        }
    }
}
// single-B variant (k_node), B area = BP_OFF
__device__ __forceinline__ void compute_chunk(uint32_t buf, const Frag& f, float (*d)[4][4]) {
#pragma unroll
    for (int ks = 0; ks < 4; ++ks) {
        const uint32_t aoff = (((f.aC0 + 2 * ks) * 16) ^ f.aMask);
        uint32_t a[4][4];
#pragma unroll
        for (int mf = 0; mf < 4; ++mf)
            ldsm_x4(a[mf], buf + f.aOff + mf * 2048 + aoff);
        const uint32_t boff = f.bRel + (((f.bC0 + 2 * ks) * 16) ^ f.bMask);
#pragma unroll
        for (int p = 0; p < 2; ++p) {
            uint32_t b[4];
            ldsm_x4(b, buf + BP_OFF + p * 2048 + boff);
#pragma unroll
            for (int sub = 0; sub < 2; ++sub)
#pragma unroll
                for (int mf = 0; mf < 4; ++mf)
                    mma_f16(d[mf][p * 2 + sub], a[mf], b + 2 * sub);
        }
    }
}

// ================= fused edge kernel =================
// messages = relu([h_u, e] @ P + pb) -> red.v4 scatter into g_agg
// e_new    = relu([e, h_u, h_v] @ W + wb) -> stg.128
__global__ __launch_bounds__(256, 1) void k_edge(const float* __restrict__ Pb,
                                                 const float* __restrict__ Wb,
                                                 float* __restrict__ oute) {
    extern __shared__ char smem[];
    const uint32_t sb = smem_u32(smem);
    const int tid = threadIdx.x, lane = tid & 31, warp = tid >> 5;
    const int e0 = blockIdx.x * 128;
    const int frow = tid >> 1, fhalf = tid & 1;
    const int feg = e0 + frow;
    const int fegc = (feg < NEDGES) ? feg : (NEDGES - 1);
    const int fsrc = g_src[fegc];
    const int ftgt = g_tgt[fegc];
    const Frag f = make_frag(warp, lane);

    float dP[4][4][4], dW[4][4][4];
#pragma unroll
    for (int i = 0; i < 4; ++i)
#pragma unroll
        for (int j = 0; j < 4; ++j)
#pragma unroll
            for (int k = 0; k < 4; ++k) { dP[i][j][k] = 0.f; dW[i][j][k] = 0.f; }

    // A chunks: 0,1 = e; 2,3 = h_u; 4,5 = h_v   (W chunk = ch; P chunk = pmap)
    const uint32_t* as[6] = {g_e16 + (size_t)fegc * 64 + fhalf * 16,
                             g_e16 + (size_t)fegc * 64 + 32 + fhalf * 16,
                             g_h16 + (size_t)fsrc * 64 + fhalf * 16,
                             g_h16 + (size_t)fsrc * 64 + 32 + fhalf * 16,
                             g_h16 + (size_t)ftgt * 64 + fhalf * 16,
                             g_h16 + (size_t)ftgt * 64 + 32 + fhalf * 16};
    // pmap(ch): e -> P chunks 2,3; h_u -> P chunks 0,1; h_v -> none
    auto pmap = [](int ch) { return (ch < 2) ? ch + 2 : ((ch < 4) ? ch - 2 : -1); };

    fill_a_async(sb, frow, fhalf, as[0]);
    fill_b_async(sb, BW_OFF, g_imgW, 0, tid);
    fill_b_async(sb, BP_OFF, g_imgP, pmap(0), tid);
    cpa_commit();
#pragma unroll 1
    for (int ch = 0; ch < 6; ++ch) {
        const uint32_t buf = sb + (ch & 1) * BUFSZ;
        if (ch + 1 < 6) {
            const uint32_t nbuf = sb + ((ch + 1) & 1) * BUFSZ;
            fill_a_async(nbuf, frow, fhalf, as[ch + 1]);
            fill_b_async(nbuf, BW_OFF, g_imgW, ch + 1, tid);
            if (pmap(ch + 1) >= 0) fill_b_async(nbuf, BP_OFF, g_imgP, pmap(ch + 1), tid);
            cpa_commit();
            cpa_wait<1>();
        } else {
            cpa_wait<0>();
        }
        __syncthreads();
        compute_chunk_dual(buf, f, dW, dP, ch < 4);
        __syncthreads();
    }

    const int mh = warp >> 2, ws = warp & 3;
    const int r4 = lane >> 2, c2 = (lane & 3) * 2;
    const bool evenlane = ((lane & 1) == 0);
#pragma unroll
    for (int mf = 0; mf < 4; ++mf) {
#pragma unroll
        for (int half = 0; half < 2; ++half) {
            const int eg = e0 + mh * 64 + mf * 16 + r4 + half * 8;
            const bool valid = eg < NEDGES;
            const int egc = valid ? eg : (NEDGES - 1);
            float* arow = g_agg + (size_t)__ldg(&g_tgt[egc]) * DIM;
            float* orow = oute + (size_t)egc * DIM;
#pragma unroll
            for (int nfl = 0; nfl < 4; ++nfl) {
                const int col = ws * 32 + nfl * 8 + c2;
                float2 bP = __ldg((const float2*)(Pb + col));
                float2 bW = __ldg((const float2*)(Wb + col));
                float2 vP, vW;
                vP.x = fmaxf(dP[mf][nfl][half * 2 + 0] + bP.x, 0.f);
                vP.y = fmaxf(dP[mf][nfl][half * 2 + 1] + bP.y, 0.f);
                vW.x = fmaxf(dW[mf][nfl][half * 2 + 0] + bW.x, 0.f);
                vW.y = fmaxf(dW[mf][nfl][half * 2 + 1] + bW.y, 0.f);
                // merge with partner lane (cols col+2, col+3)
                float pPx = __shfl_xor_sync(0xffffffffu, vP.x, 1);
                float pPy = __shfl_xor_sync(0xffffffffu, vP.y, 1);
                float pWx = __shfl_xor_sync(0xffffffffu, vW.x, 1);
                float pWy = __shfl_xor_sync(0xffffffffu, vW.y, 1);
                if (valid && evenlane) {
                    red_v4(arow + col, vP.x, vP.y, pPx, pPy);
                    float4 s = make_float4(vW.x, vW.y, pWx, pWy);
                    *(float4*)(orow + col) = s;
                }
            }
        }
    }
}

// ================= node kernel =================
__global__ __launch_bounds__(256, 1) void k_node(const float* __restrict__ Qb,
                                                 float* __restrict__ outh) {
    extern __shared__ char smem[];
    const uint32_t sb = smem_u32(smem);
    const int tid = threadIdx.x, lane = tid & 31, warp = tid >> 5;
    const int n0 = blockIdx.x * 128;
    const int frow = tid >> 1, fhalf = tid & 1;
    const int fng = n0 + frow;
    const int fnode = (fng < NNODES) ? fng : (NNODES - 1);
    const float finvd = 1.f / fmaxf(g_deg[fnode], 1.f);
    const Frag f = make_frag(warp, lane);

    float d[4][4][4];
#pragma unroll
    for (int i = 0; i < 4; ++i)
#pragma unroll
        for (int j = 0; j < 4; ++j)
#pragma unroll
            for (int k = 0; k < 4; ++k) d[i][j][k] = 0.f;

    const uint32_t* as[2] = {g_h16 + (size_t)fnode * 64 + fhalf * 16,
                             g_h16 + (size_t)fnode * 64 + 32 + fhalf * 16};

    // chunks: 0,1 = h (async); 2,3 = agg*invdeg (register path)
    fill_a_async(sb, frow, fhalf, as[0]);
    fill_b_async(sb, BP_OFF, g_imgQ, 0, tid);
    cpa_commit();
#pragma unroll 1
    for (int ch = 0; ch < 4; ++ch) {
        const uint32_t buf = sb + (ch & 1) * BUFSZ;
        if (ch + 1 < 4) {
            const uint32_t nbuf = sb + ((ch + 1) & 1) * BUFSZ;
            const uint32_t nofs = ((ch + 1) & 1) * BUFSZ;
            if (ch + 1 < 2) fill_a_async(nbuf, frow, fhalf, as[ch + 1]);
            else fill_a_f32(smem, nofs, frow, fhalf,
                            g_agg + (size_t)fnode * DIM + (ch + 1 - 2) * 64, finvd);
            fill_b_async(nbuf, BP_OFF, g_imgQ, ch + 1, tid);
            cpa_commit();
            cpa_wait<1>();
        } else {
            cpa_wait<0>();
        }
        __syncthreads();
        compute_chunk(buf, f, d);
        __syncthreads();
    }

    const int mh = warp >> 2, ws = warp & 3;
    const int r4 = lane >> 2, c2 = (lane & 3) * 2;
    const bool evenlane = ((lane & 1) == 0);
#pragma unroll
    for (int mf = 0; mf < 4; ++mf) {
#pragma unroll
        for (int half = 0; half < 2; ++half) {
            const int ng = n0 + mh * 64 + mf * 16 + r4 + half * 8;
            const bool valid = ng < NNODES;
            float* orow = outh + (size_t)(valid ? ng : 0) * DIM;
#pragma unroll
            for (int nfl = 0; nfl < 4; ++nfl) {
                const int col = ws * 32 + nfl * 8 + c2;
                float2 bias = __ldg((const float2*)(Qb + col));
                float2 v;
                v.x = fmaxf(d[mf][nfl][half * 2 + 0] + bias.x, 0.f);
                v.y = fmaxf(d[mf][nfl][half * 2 + 1] + bias.y, 0.f);
                float px = __shfl_xor_sync(0xffffffffu, v.x, 1);
                float py = __shfl_xor_sync(0xffffffffu, v.y, 1);
                if (valid && evenlane)
                    *(float4*)(orow + col) = make_float4(v.x, v.y, px, py);
            }
        }
    }
}

extern "C" void kernel_launch(void* const* d_in, const int* in_sizes, int n_in,
                              void* d_out, int out_size) {
    const float* h    = (const float*)d_in[0];
    const float* e    = (const float*)d_in[1];
    const void*  eidx = d_in[2];
    const float* Pw   = (const float*)d_in[3];
    const float* Pb   = (const float*)d_in[4];
    const float* Qw   = (const float*)d_in[5];
    const float* Qb   = (const float*)d_in[6];
    const float* Ww   = (const float*)d_in[7];
    const float* Wb   = (const float*)d_in[8];

    float* outh = (float*)d_out;
    float* oute = outh + (size_t)NNODES * DIM;

    cudaFuncSetAttribute(k_edge, cudaFuncAttributeMaxDynamicSharedMemorySize, SMEM_BYTES);
    cudaFuncSetAttribute(k_node, cudaFuncAttributeMaxDynamicSharedMemorySize, SMEM_BYTES);

    const int dblocks = (NEDGES + 255) / 256;
    const int eg = (NEDGES + 127) / 128;   // 4883
    const int ng = (NNODES + 127) / 128;   // 782

    detect_idx<<<1, 32>>>(eidx);
    decode_idx<<<dblocks, 256>>>(eidx);
    count_deg<<<dblocks, 256>>>();
    prep_h<<<(NNODES * 32 + 255) / 256, 256>>>(h);
    prep_e<<<(NEDGES * 32 + 255) / 256, 256>>>(e);
    prep_w<<<64, 256>>>(Pw, 0, 4);
    prep_w<<<64, 256>>>(Qw, 1, 4);
    prep_w<<<96, 256>>>(Ww, 2, 6);
    k_edge<<<eg, 256, SMEM_BYTES>>>(Pb, Wb, oute);
    k_node<<<ng, 256, SMEM_BYTES>>>(Qb, outh);
}

// round 10
// speedup vs baseline: 2.0486x; 1.0264x over previous
#include <cuda_runtime.h>
#include <cstdint>

#define NNODES 100000
#define NEDGES 625000
#define DIM 128

// ---- per-buffer smem layout; two buffers of 48KB ----
#define A_OFF 0           // 128 rows x 128B, swizzled fp16 k-major
#define BP_OFF 16384      // P-weight chunk (128 n-rows x 128B)
#define BW_OFF 32768      // W-weight chunk
#define BUFSZ 49152
#define SMEM_BYTES (2 * BUFSZ)

// ---- device scratch ----
__device__ float g_agg[(size_t)NNODES * DIM];
__device__ float g_deg[NNODES];
__device__ int g_src[NEDGES];
__device__ int g_tgt[NEDGES];
__device__ int g_is64;
__device__ uint32_t g_h16[(size_t)NNODES * 64];   // fp16x2-packed h rows
__device__ uint32_t g_imgP[4 * 4096];             // swizzled fp16 weight images
__device__ uint32_t g_imgQ[4 * 4096];
__device__ uint32_t g_imgW[6 * 4096];

// ================= helpers =================
__device__ __forceinline__ uint32_t smem_u32(const void* p) {
    uint32_t a;
    asm("{ .reg .u64 t; cvta.to.shared.u64 t, %1; cvt.u32.u64 %0, t; }" : "=r"(a) : "l"(p));
    return a;
}
__device__ __forceinline__ uint32_t cvt_f16x2(float x, float y) {
    uint32_t r;
    asm("cvt.rn.f16x2.f32 %0, %2, %1;" : "=r"(r) : "f"(x), "f"(y));
    return r;
}
__device__ __forceinline__ void ldsm_x4(uint32_t* r, uint32_t addr) {
    asm volatile("ldmatrix.sync.aligned.m8n8.x4.shared.b16 {%0,%1,%2,%3}, [%4];"
                 : "=r"(r[0]), "=r"(r[1]), "=r"(r[2]), "=r"(r[3]) : "r"(addr));
}
__device__ __forceinline__ void mma_f16(float* d, const uint32_t* a, const uint32_t* b) {
    asm volatile(
        "mma.sync.aligned.m16n8k16.row.col.f32.f16.f16.f32 "
        "{%0,%1,%2,%3}, {%4,%5,%6,%7}, {%8,%9}, {%0,%1,%2,%3};"
        : "+f"(d[0]), "+f"(d[1]), "+f"(d[2]), "+f"(d[3])
        : "r"(a[0]), "r"(a[1]), "r"(a[2]), "r"(a[3]), "r"(b[0]), "r"(b[1]));
}
__device__ __forceinline__ void cpa16(uint32_t dst, const void* src) {
    asm volatile("cp.async.cg.shared.global [%0], [%1], 16;" :: "r"(dst), "l"(src));
}
__device__ __forceinline__ void cpa_commit() {
    asm volatile("cp.async.commit_group;" ::: "memory");
}
template <int N>
__device__ __forceinline__ void cpa_wait() {
    asm volatile("cp.async.wait_group %0;" :: "n"(N) : "memory");
}
__device__ __forceinline__ void red_v4(float* ptr, float a, float b, float c, float d) {
    asm volatile("red.global.v4.f32.add [%0], {%1, %2, %3, %4};"
                 :: "l"(ptr), "f"(a), "f"(b), "f"(c), "f"(d) : "memory");
}

// ================= prep kernels =================
__global__ void detect_idx(const void* ei) {
    if (threadIdx.x == 0 && blockIdx.x == 0) {
        const unsigned long long* p = (const unsigned long long*)ei;
        int is64 = 1;
        for (int i = 0; i < 64; ++i)
            if (p[i] >= (unsigned long long)NNODES) { is64 = 0; break; }
        g_is64 = is64;
    }
}
// decode indices + zero agg/deg; then count degrees (atomic) in the same pass
__global__ void decode_idx(const void* ei) {
    int i = blockIdx.x * blockDim.x + threadIdx.x;
    size_t stride = (size_t)gridDim.x * blockDim.x;
    for (size_t j = i; j < (size_t)NNODES * DIM; j += stride) g_agg[j] = 0.f;
    for (size_t j = i; j < NNODES; j += stride) g_deg[j] = 0.f;
    if (i < NEDGES) {
        long long s, t;
        if (g_is64) { s = ((const long long*)ei)[i]; t = ((const long long*)ei)[NEDGES + i]; }
        else        { s = ((const int*)ei)[i];       t = ((const int*)ei)[NEDGES + i]; }
        if (s < 0) s = 0; if (s >= NNODES) s = NNODES - 1;
        if (t < 0) t = 0; if (t >= NNODES) t = NNODES - 1;
        g_src[i] = (int)s; g_tgt[i] = (int)t;
    }
}
__global__ void count_deg() {
    int i = blockIdx.x * blockDim.x + threadIdx.x;
    if (i < NEDGES) atomicAdd(&g_deg[g_tgt[i]], 1.f);
}
__global__ void prep_h(const float* __restrict__ h) {
    size_t id = (size_t)blockIdx.x * blockDim.x + threadIdx.x;
    if (id >= (size_t)NNODES * 32) return;
    float4 v = ((const float4*)h)[id];
    ((uint2*)g_h16)[id] = make_uint2(cvt_f16x2(v.x, v.y), cvt_f16x2(v.z, v.w));
}
// all three weight images in one launch: chunks 0-3 = P, 4-7 = Q, 8-13 = W
__global__ void prep_w_all(const float* __restrict__ Pw, const float* __restrict__ Qw,
                           const float* __restrict__ Ww) {
    int id = blockIdx.x * blockDim.x + threadIdx.x;
    if (id >= 14 * 4096) return;
    int chunk = id >> 12, pos = id & 4095;
    const float* src;
    uint32_t* dst;
    int c;
    if (chunk < 4)      { src = Pw; dst = g_imgP; c = chunk; }
    else if (chunk < 8) { src = Qw; dst = g_imgQ; c = chunk - 4; }
    else                { src = Ww; dst = g_imgW; c = chunk - 8; }
    int n = pos >> 5, kp = pos & 31;
    uint32_t off = n * 128 + kp * 4;
    uint32_t swz = off ^ ((off >> 3) & 0x70);
    int k0 = c * 64 + kp * 2;
    float x = src[(size_t)k0 * DIM + n];
    float y = src[(size_t)(k0 + 1) * DIM + n];
    dst[(c << 12) + (swz >> 2)] = cvt_f16x2(x, y);
}

// ================= fills =================
__device__ __forceinline__ void fill_a_async(uint32_t buf, int row, int half,
                                             const uint32_t* src) {
    const uint32_t mask = (uint32_t)((row & 7) << 4);
    const uint32_t rowbase = buf + A_OFF + (uint32_t)(row * 128);
#pragma unroll
    for (int i = 0; i < 4; ++i) {
        uint32_t off = (((uint32_t)((half * 4 + i) * 16)) ^ mask);
        cpa16(rowbase + off, src + i * 4);
    }
}
// register-path fill: LDG fp32 + cvt + STS (used for e chunks and agg chunks)
__device__ __forceinline__ void fill_a_f32(char* smem, uint32_t bufofs, int row, int half,
                                           const float* src, float sc) {
    const float4* s = (const float4*)src + half * 8;
    const uint32_t mask = (uint32_t)((row & 7) << 4);
#pragma unroll
    for (int i = 0; i < 4; ++i) {
        float4 a = s[2 * i], b = s[2 * i + 1];
        uint4 w;
        w.x = cvt_f16x2(a.x * sc, a.y * sc);
        w.y = cvt_f16x2(a.z * sc, a.w * sc);
        w.z = cvt_f16x2(b.x * sc, b.y * sc);
        w.w = cvt_f16x2(b.z * sc, b.w * sc);
        uint32_t off = (uint32_t)(row * 128) + (((uint32_t)((half * 4 + i) * 16)) ^ mask);
        *(uint4*)(smem + bufofs + A_OFF + off) = w;
    }
}
__device__ __forceinline__ void fill_b_async(uint32_t buf, uint32_t area,
                                             const uint32_t* img, int ch, int tid) {
    const uint32_t* s = img + ((size_t)ch << 12) + tid * 4;
#pragma unroll
    for (int i = 0; i < 4; ++i)
        cpa16(buf + area + (uint32_t)((i * 256 + tid) * 16), s + i * 1024);
}

// ================= compute =================
struct Frag {
    uint32_t aOff, aMask, aC0;
    uint32_t bRel, bMask, bC0;
};
__device__ __forceinline__ Frag make_frag(int warp, int lane) {
    Frag f;
    const int mh = warp >> 2, ws = warp & 3;
    f.aOff = A_OFF + (uint32_t)((mh * 64 + (lane & 15)) * 128);
    f.aMask = (uint32_t)((lane & 7) << 4);
    f.aC0 = (uint32_t)(lane >> 4);
    f.bRel = (uint32_t)(ws * 4096 + (lane & 7) * 128 + ((lane >> 4) & 1) * 1024);
    f.bMask = (uint32_t)((lane & 7) << 4);
    f.bC0 = (uint32_t)((lane >> 3) & 1);
    return f;
}
__device__ __forceinline__ void compute_chunk_dual(uint32_t buf, const Frag& f,
                                                   float (*dW)[4][4], float (*dP)[4][4],
                                                   bool hasP) {
#pragma unroll
    for (int ks = 0; ks < 4; ++ks) {
        const uint32_t aoff = (((f.aC0 + 2 * ks) * 16) ^ f.aMask);
        uint32_t a[4][4];
#pragma unroll
        for (int mf = 0; mf < 4; ++mf)
            ldsm_x4(a[mf], buf + f.aOff + mf * 2048 + aoff);
        const uint32_t boff = f.bRel + (((f.bC0 + 2 * ks) * 16) ^ f.bMask);
#pragma unroll
        for (int p = 0; p < 2; ++p) {
            uint32_t b[4];
            ldsm_x4(b, buf + BW_OFF + p * 2048 + boff);
#pragma unroll
            for (int sub = 0; sub < 2; ++sub)
#pragma unroll
                for (int mf = 0; mf < 4; ++mf)
                    mma_f16(dW[mf][p * 2 + sub], a[mf], b + 2 * sub);
            if (hasP) {
                uint32_t bp[4];
                ldsm_x4(bp, buf + BP_OFF + p * 2048 + boff);
#pragma unroll
                for (int sub = 0; sub < 2; ++sub)
#pragma unroll
                    for (int mf = 0; mf < 4; ++mf)
                        mma_f16(dP[mf][p * 2 + sub], a[mf], bp + 2 * sub);
            }
        }
    }
}
__device__ __forceinline__ void compute_chunk(uint32_t buf, const Frag& f, float (*d)[4][4]) {
#pragma unroll
    for (int ks = 0; ks < 4; ++ks) {
        const uint32_t aoff = (((f.aC0 + 2 * ks) * 16) ^ f.aMask);
        uint32_t a[4][4];
#pragma unroll
        for (int mf = 0; mf < 4; ++mf)
            ldsm_x4(a[mf], buf + f.aOff + mf * 2048 + aoff);
        const uint32_t boff = f.bRel + (((f.bC0 + 2 * ks) * 16) ^ f.bMask);
#pragma unroll
        for (int p = 0; p < 2; ++p) {
            uint32_t b[4];
            ldsm_x4(b, buf + BP_OFF + p * 2048 + boff);
#pragma unroll
            for (int sub = 0; sub < 2; ++sub)
#pragma unroll
                for (int mf = 0; mf < 4; ++mf)
                    mma_f16(d[mf][p * 2 + sub], a[mf], b + 2 * sub);
        }
    }
}

// ================= fused edge kernel =================
// messages = relu([h_u, e] @ P + pb) -> red.v4 scatter into g_agg
// e_new    = relu([e, h_u, h_v] @ W + wb) -> stg.128
__global__ __launch_bounds__(256, 1) void k_edge(const float* __restrict__ Pb,
                                                 const float* __restrict__ Wb,
                                                 const float* __restrict__ e,
                                                 float* __restrict__ oute) {
    extern __shared__ char smem[];
    const uint32_t sb = smem_u32(smem);
    const int tid = threadIdx.x, lane = tid & 31, warp = tid >> 5;
    const int e0 = blockIdx.x * 128;
    const int frow = tid >> 1, fhalf = tid & 1;
    const int feg = e0 + frow;
    const int fegc = (feg < NEDGES) ? feg : (NEDGES - 1);
    const int fsrc = g_src[fegc];
    const int ftgt = g_tgt[fegc];
    const Frag f = make_frag(warp, lane);

    float dP[4][4][4], dW[4][4][4];
#pragma unroll
    for (int i = 0; i < 4; ++i)
#pragma unroll
        for (int j = 0; j < 4; ++j)
#pragma unroll
            for (int k = 0; k < 4; ++k) { dP[i][j][k] = 0.f; dW[i][j][k] = 0.f; }

    // A chunks: 0,1 = e (fp32 register-path convert); 2,3 = h_u; 4,5 = h_v (cp.async)
    const float* e_row = e + (size_t)fegc * DIM;
    const uint32_t* ah[6] = {nullptr, nullptr,
                             g_h16 + (size_t)fsrc * 64 + fhalf * 16,
                             g_h16 + (size_t)fsrc * 64 + 32 + fhalf * 16,
                             g_h16 + (size_t)ftgt * 64 + fhalf * 16,
                             g_h16 + (size_t)ftgt * 64 + 32 + fhalf * 16};
    // pmap(ch): e -> P chunks 2,3; h_u -> P chunks 0,1; h_v -> none
    auto pmap = [](int ch) { return (ch < 2) ? ch + 2 : ((ch < 4) ? ch - 2 : -1); };

    fill_a_f32(smem, 0, frow, fhalf, e_row, 1.f);          // chunk 0 = e[0:64]
    fill_b_async(sb, BW_OFF, g_imgW, 0, tid);
    fill_b_async(sb, BP_OFF, g_imgP, pmap(0), tid);
    cpa_commit();
#pragma unroll 1
    for (int ch = 0; ch < 6; ++ch) {
        const uint32_t buf = sb + (ch & 1) * BUFSZ;
        if (ch + 1 < 6) {
            const uint32_t nbuf = sb + ((ch + 1) & 1) * BUFSZ;
            const uint32_t nofs = ((ch + 1) & 1) * BUFSZ;
            if (ch + 1 < 2) fill_a_f32(smem, nofs, frow, fhalf, e_row + 64, 1.f);
            else fill_a_async(nbuf, frow, fhalf, ah[ch + 1]);
            fill_b_async(nbuf, BW_OFF, g_imgW, ch + 1, tid);
            if (pmap(ch + 1) >= 0) fill_b_async(nbuf, BP_OFF, g_imgP, pmap(ch + 1), tid);
            cpa_commit();
            cpa_wait<1>();
        } else {
            cpa_wait<0>();
        }
        __syncthreads();
        compute_chunk_dual(buf, f, dW, dP, ch < 4);
        __syncthreads();
    }

    const int mh = warp >> 2, ws = warp & 3;
    const int r4 = lane >> 2, c2 = (lane & 3) * 2;
    const bool evenlane = ((lane & 1) == 0);
#pragma unroll
    for (int mf = 0; mf < 4; ++mf) {
#pragma unroll
        for (int half = 0; half < 2; ++half) {
            const int eg = e0 + mh * 64 + mf * 16 + r4 + half * 8;
            const bool valid = eg < NEDGES;
            const int egc = valid ? eg : (NEDGES - 1);
            float* arow = g_agg + (size_t)__ldg(&g_tgt[egc]) * DIM;
            float* orow = oute + (size_t)egc * DIM;
#pragma unroll
            for (int nfl = 0; nfl < 4; ++nfl) {
                const int col = ws * 32 + nfl * 8 + c2;
                float2 bP = __ldg((const float2*)(Pb + col));
                float2 bW = __ldg((const float2*)(Wb + col));
                float2 vP, vW;
                vP.x = fmaxf(dP[mf][nfl][half * 2 + 0] + bP.x, 0.f);
                vP.y = fmaxf(dP[mf][nfl][half * 2 + 1] + bP.y, 0.f);
                vW.x = fmaxf(dW[mf][nfl][half * 2 + 0] + bW.x, 0.f);
                vW.y = fmaxf(dW[mf][nfl][half * 2 + 1] + bW.y, 0.f);
                float pPx = __shfl_xor_sync(0xffffffffu, vP.x, 1);
                float pPy = __shfl_xor_sync(0xffffffffu, vP.y, 1);
                float pWx = __shfl_xor_sync(0xffffffffu, vW.x, 1);
                float pWy = __shfl_xor_sync(0xffffffffu, vW.y, 1);
                if (valid && evenlane) {
                    red_v4(arow + col, vP.x, vP.y, pPx, pPy);
                    *(float4*)(orow + col) = make_float4(vW.x, vW.y, pWx, pWy);
                }
            }
        }
    }
}

// ================= node kernel =================
__global__ __launch_bounds__(256, 1) void k_node(const float* __restrict__ Qb,
                                                 float* __restrict__ outh) {
    extern __shared__ char smem[];
    const uint32_t sb = smem_u32(smem);
    const int tid = threadIdx.x, lane = tid & 31, warp = tid >> 5;
    const int n0 = blockIdx.x * 128;
    const int frow = tid >> 1, fhalf = tid & 1;
    const int fng = n0 + frow;
    const int fnode = (fng < NNODES) ? fng : (NNODES - 1);
    const float finvd = 1.f / fmaxf(g_deg[fnode], 1.f);
    const Frag f = make_frag(warp, lane);

    float d[4][4][4];
#pragma unroll
    for (int i = 0; i < 4; ++i)
#pragma unroll
        for (int j = 0; j < 4; ++j)
#pragma unroll
            for (int k = 0; k < 4; ++k) d[i][j][k] = 0.f;

    const uint32_t* as[2] = {g_h16 + (size_t)fnode * 64 + fhalf * 16,
                             g_h16 + (size_t)fnode * 64 + 32 + fhalf * 16};

    // chunks: 0,1 = h (async); 2,3 = agg*invdeg (register path)
    fill_a_async(sb, frow, fhalf, as[0]);
    fill_b_async(sb, BP_OFF, g_imgQ, 0, tid);
    cpa_commit();
#pragma unroll 1
    for (int ch = 0; ch < 4; ++ch) {
        const uint32_t buf = sb + (ch & 1) * BUFSZ;
        if (ch + 1 < 4) {
            const uint32_t nbuf = sb + ((ch + 1) & 1) * BUFSZ;
            const uint32_t nofs = ((ch + 1) & 1) * BUFSZ;
            if (ch + 1 < 2) fill_a_async(nbuf, frow, fhalf, as[ch + 1]);
            else fill_a_f32(smem, nofs, frow, fhalf,
                            g_agg + (size_t)fnode * DIM + (ch + 1 - 2) * 64, finvd);
            fill_b_async(nbuf, BP_OFF, g_imgQ, ch + 1, tid);
            cpa_commit();
            cpa_wait<1>();
        } else {
            cpa_wait<0>();
        }
        __syncthreads();
        compute_chunk(buf, f, d);
        __syncthreads();
    }

    const int mh = warp >> 2, ws = warp & 3;
    const int r4 = lane >> 2, c2 = (lane & 3) * 2;
    const bool evenlane = ((lane & 1) == 0);
#pragma unroll
    for (int mf = 0; mf < 4; ++mf) {
#pragma unroll
        for (int half = 0; half < 2; ++half) {
            const int ng = n0 + mh * 64 + mf * 16 + r4 + half * 8;
            const bool valid = ng < NNODES;
            float* orow = outh + (size_t)(valid ? ng : 0) * DIM;
#pragma unroll
            for (int nfl = 0; nfl < 4; ++nfl) {
                const int col = ws * 32 + nfl * 8 + c2;
                float2 bias = __ldg((const float2*)(Qb + col));
                float2 v;
                v.x = fmaxf(d[mf][nfl][half * 2 + 0] + bias.x, 0.f);
                v.y = fmaxf(d[mf][nfl][half * 2 + 1] + bias.y, 0.f);
                float px = __shfl_xor_sync(0xffffffffu, v.x, 1);
                float py = __shfl_xor_sync(0xffffffffu, v.y, 1);
                if (valid && evenlane)
                    *(float4*)(orow + col) = make_float4(v.x, v.y, px, py);
            }
        }
    }
}

extern "C" void kernel_launch(void* const* d_in, const int* in_sizes, int n_in,
                              void* d_out, int out_size) {
    const float* h    = (const float*)d_in[0];
    const float* e    = (const float*)d_in[1];
    const void*  eidx = d_in[2];
    const float* Pw   = (const float*)d_in[3];
    const float* Pb   = (const float*)d_in[4];
    const float* Qw   = (const float*)d_in[5];
    const float* Qb   = (const float*)d_in[6];
    const float* Ww   = (const float*)d_in[7];
    const float* Wb   = (const float*)d_in[8];

    float* outh = (float*)d_out;
    float* oute = outh + (size_t)NNODES * DIM;

    cudaFuncSetAttribute(k_edge, cudaFuncAttributeMaxDynamicSharedMemorySize, SMEM_BYTES);
    cudaFuncSetAttribute(k_node, cudaFuncAttributeMaxDynamicSharedMemorySize, SMEM_BYTES);

    const int dblocks = (NEDGES + 255) / 256;
    const int eg = (NEDGES + 127) / 128;   // 4883
    const int ng = (NNODES + 127) / 128;   // 782

    detect_idx<<<1, 32>>>(eidx);
    decode_idx<<<dblocks, 256>>>(eidx);
    count_deg<<<dblocks, 256>>>();
    prep_h<<<(NNODES * 32 + 255) / 256, 256>>>(h);
    prep_w_all<<<224, 256>>>(Pw, Qw, Ww);
    k_edge<<<eg, 256, SMEM_BYTES>>>(Pb, Wb, e, oute);
    k_node<<<ng, 256, SMEM_BYTES>>>(Qb, outh);
}

// round 11
// speedup vs baseline: 2.2498x; 1.0982x over previous
#include <cuda_runtime.h>
#include <cstdint>

#define NNODES 100000
#define NEDGES 625000
#define DIM 128
#define NT 4883           // edge tiles of 128

// ---- k_edge smem layout: resident weights + double-buffered A ----
#define BW_BASE 0         // 6 chunks x 16KB = 96KB
#define BP_BASE 98304     // 4 chunks x 16KB = 64KB
#define A_BASE  163840    // 2 x 16KB
#define SMEM_EDGE 196608
// ---- k_node: per-buffer A(16K)+B(16K), double-buffered ----
#define NBUFSZ 32768
#define SMEM_NODE 65536

// ---- device scratch ----
__device__ float g_agg[(size_t)NNODES * DIM];
__device__ float g_deg[NNODES];
__device__ int g_src[NEDGES];
__device__ int g_tgt[NEDGES];
__device__ int g_is64;
__device__ uint32_t g_h16[(size_t)NNODES * 64];   // fp16x2-packed h rows
__device__ uint32_t g_imgP[4 * 4096];             // swizzled fp16 weight images
__device__ uint32_t g_imgQ[4 * 4096];
__device__ uint32_t g_imgW[6 * 4096];

// ================= helpers =================
__device__ __forceinline__ uint32_t smem_u32(const void* p) {
    uint32_t a;
    asm("{ .reg .u64 t; cvta.to.shared.u64 t, %1; cvt.u32.u64 %0, t; }" : "=r"(a) : "l"(p));
    return a;
}
__device__ __forceinline__ uint32_t cvt_f16x2(float x, float y) {
    uint32_t r;
    asm("cvt.rn.f16x2.f32 %0, %2, %1;" : "=r"(r) : "f"(x), "f"(y));
    return r;
}
__device__ __forceinline__ void ldsm_x4(uint32_t* r, uint32_t addr) {
    asm volatile("ldmatrix.sync.aligned.m8n8.x4.shared.b16 {%0,%1,%2,%3}, [%4];"
                 : "=r"(r[0]), "=r"(r[1]), "=r"(r[2]), "=r"(r[3]) : "r"(addr));
}
__device__ __forceinline__ void mma_f16(float* d, const uint32_t* a, const uint32_t* b) {
    asm volatile(
        "mma.sync.aligned.m16n8k16.row.col.f32.f16.f16.f32 "
        "{%0,%1,%2,%3}, {%4,%5,%6,%7}, {%8,%9}, {%0,%1,%2,%3};"
        : "+f"(d[0]), "+f"(d[1]), "+f"(d[2]), "+f"(d[3])
        : "r"(a[0]), "r"(a[1]), "r"(a[2]), "r"(a[3]), "r"(b[0]), "r"(b[1]));
}
__device__ __forceinline__ void cpa16(uint32_t dst, const void* src) {
    asm volatile("cp.async.cg.shared.global [%0], [%1], 16;" :: "r"(dst), "l"(src));
}
__device__ __forceinline__ void cpa_commit() {
    asm volatile("cp.async.commit_group;" ::: "memory");
}
template <int N>
__device__ __forceinline__ void cpa_wait() {
    asm volatile("cp.async.wait_group %0;" :: "n"(N) : "memory");
}
__device__ __forceinline__ void red_v4(float* ptr, float a, float b, float c, float d) {
    asm volatile("red.global.v4.f32.add [%0], {%1, %2, %3, %4};"
                 :: "l"(ptr), "f"(a), "f"(b), "f"(c), "f"(d) : "memory");
}

// ================= prep kernels =================
__global__ void detect_idx(const void* ei) {
    if (threadIdx.x == 0 && blockIdx.x == 0) {
        const unsigned long long* p = (const unsigned long long*)ei;
        int is64 = 1;
        for (int i = 0; i < 64; ++i)
            if (p[i] >= (unsigned long long)NNODES) { is64 = 0; break; }
        g_is64 = is64;
    }
}
__global__ void decode_idx(const void* ei) {
    int i = blockIdx.x * blockDim.x + threadIdx.x;
    size_t stride = (size_t)gridDim.x * blockDim.x;
    for (size_t j = i; j < (size_t)NNODES * DIM; j += stride) g_agg[j] = 0.f;
    for (size_t j = i; j < NNODES; j += stride) g_deg[j] = 0.f;
    if (i < NEDGES) {
        long long s, t;
        if (g_is64) { s = ((const long long*)ei)[i]; t = ((const long long*)ei)[NEDGES + i]; }
        else        { s = ((const int*)ei)[i];       t = ((const int*)ei)[NEDGES + i]; }
        if (s < 0) s = 0; if (s >= NNODES) s = NNODES - 1;
        if (t < 0) t = 0; if (t >= NNODES) t = NNODES - 1;
        g_src[i] = (int)s; g_tgt[i] = (int)t;
    }
}
__global__ void count_deg() {
    int i = blockIdx.x * blockDim.x + threadIdx.x;
    if (i < NEDGES) atomicAdd(&g_deg[g_tgt[i]], 1.f);
}
__global__ void prep_h(const float* __restrict__ h) {
    size_t id = (size_t)blockIdx.x * blockDim.x + threadIdx.x;
    if (id >= (size_t)NNODES * 32) return;
    float4 v = ((const float4*)h)[id];
    ((uint2*)g_h16)[id] = make_uint2(cvt_f16x2(v.x, v.y), cvt_f16x2(v.z, v.w));
}
__global__ void prep_w_all(const float* __restrict__ Pw, const float* __restrict__ Qw,
                           const float* __restrict__ Ww) {
    int id = blockIdx.x * blockDim.x + threadIdx.x;
    if (id >= 14 * 4096) return;
    int chunk = id >> 12, pos = id & 4095;
    const float* src;
    uint32_t* dst;
    int c;
    if (chunk < 4)      { src = Pw; dst = g_imgP; c = chunk; }
    else if (chunk < 8) { src = Qw; dst = g_imgQ; c = chunk - 4; }
    else                { src = Ww; dst = g_imgW; c = chunk - 8; }
    int n = pos >> 5, kp = pos & 31;
    uint32_t off = n * 128 + kp * 4;
    uint32_t swz = off ^ ((off >> 3) & 0x70);
    int k0 = c * 64 + kp * 2;
    float x = src[(size_t)k0 * DIM + n];
    float y = src[(size_t)(k0 + 1) * DIM + n];
    dst[(c << 12) + (swz >> 2)] = cvt_f16x2(x, y);
}

// ================= fills =================
// cp.async A fill: abase = smem addr of the A chunk region
__device__ __forceinline__ void fill_a_async(uint32_t abase, int row, int half,
                                             const uint32_t* src) {
    const uint32_t mask = (uint32_t)((row & 7) << 4);
    const uint32_t rowbase = abase + (uint32_t)(row * 128);
#pragma unroll
    for (int i = 0; i < 4; ++i) {
        uint32_t off = (((uint32_t)((half * 4 + i) * 16)) ^ mask);
        cpa16(rowbase + off, src + i * 4);
    }
}
// split register path: lda8 issues LDGs; sta8 converts + STS later
__device__ __forceinline__ void lda8(const float* src, int half, float4* pre) {
    const float4* s = (const float4*)src + half * 8;
#pragma unroll
    for (int i = 0; i < 8; ++i) pre[i] = s[i];
}
__device__ __forceinline__ void sta8(char* smem, uint32_t bufofs, int row, int half,
                                     const float4* pre) {
    const uint32_t mask = (uint32_t)((row & 7) << 4);
#pragma unroll
    for (int i = 0; i < 4; ++i) {
        uint4 w;
        w.x = cvt_f16x2(pre[2 * i].x, pre[2 * i].y);
        w.y = cvt_f16x2(pre[2 * i].z, pre[2 * i].w);
        w.z = cvt_f16x2(pre[2 * i + 1].x, pre[2 * i + 1].y);
        w.w = cvt_f16x2(pre[2 * i + 1].z, pre[2 * i + 1].w);
        uint32_t off = (uint32_t)(row * 128) + (((uint32_t)((half * 4 + i) * 16)) ^ mask);
        *(uint4*)(smem + bufofs + off) = w;
    }
}
// combined register path (k_node agg chunks, with scale)
__device__ __forceinline__ void fill_a_f32(char* smem, uint32_t bufofs, int row, int half,
                                           const float* src, float sc) {
    const float4* s = (const float4*)src + half * 8;
    const uint32_t mask = (uint32_t)((row & 7) << 4);
#pragma unroll
    for (int i = 0; i < 4; ++i) {
        float4 a = s[2 * i], b = s[2 * i + 1];
        uint4 w;
        w.x = cvt_f16x2(a.x * sc, a.y * sc);
        w.y = cvt_f16x2(a.z * sc, a.w * sc);
        w.z = cvt_f16x2(b.x * sc, b.y * sc);
        w.w = cvt_f16x2(b.z * sc, b.w * sc);
        uint32_t off = (uint32_t)(row * 128) + (((uint32_t)((half * 4 + i) * 16)) ^ mask);
        *(uint4*)(smem + bufofs + off) = w;
    }
}
__device__ __forceinline__ void fill_b_async(uint32_t bbase, const uint32_t* img, int ch,
                                             int tid) {
    const uint32_t* s = img + ((size_t)ch << 12) + tid * 4;
#pragma unroll
    for (int i = 0; i < 4; ++i)
        cpa16(bbase + (uint32_t)((i * 256 + tid) * 16), s + i * 1024);
}

// ================= compute =================
struct Frag {
    uint32_t aOff, aMask, aC0;
    uint32_t bRel, bMask, bC0;
};
__device__ __forceinline__ Frag make_frag(int warp, int lane) {
    Frag f;
    const int mh = warp >> 2, ws = warp & 3;
    f.aOff = (uint32_t)((mh * 64 + (lane & 15)) * 128);
    f.aMask = (uint32_t)((lane & 7) << 4);
    f.aC0 = (uint32_t)(lane >> 4);
    f.bRel = (uint32_t)(ws * 4096 + (lane & 7) * 128 + ((lane >> 4) & 1) * 1024);
    f.bMask = (uint32_t)((lane & 7) << 4);
    f.bC0 = (uint32_t)((lane >> 3) & 1);
    return f;
}
__device__ __forceinline__ void compute_chunk_dual(uint32_t aBase, uint32_t bwBase,
                                                   uint32_t bpBase, const Frag& f,
                                                   float (*dW)[4][4], float (*dP)[4][4],
                                                   bool hasP) {
#pragma unroll
    for (int ks = 0; ks < 4; ++ks) {
        const uint32_t aoff = (((f.aC0 + 2 * ks) * 16) ^ f.aMask);
        uint32_t a[4][4];
#pragma unroll
        for (int mf = 0; mf < 4; ++mf)
            ldsm_x4(a[mf], aBase + f.aOff + mf * 2048 + aoff);
        const uint32_t boff = f.bRel + (((f.bC0 + 2 * ks) * 16) ^ f.bMask);
#pragma unroll
        for (int p = 0; p < 2; ++p) {
            uint32_t b[4];
            ldsm_x4(b, bwBase + p * 2048 + boff);
#pragma unroll
            for (int sub = 0; sub < 2; ++sub)
#pragma unroll
                for (int mf = 0; mf < 4; ++mf)
                    mma_f16(dW[mf][p * 2 + sub], a[mf], b + 2 * sub);
            if (hasP) {
                uint32_t bp[4];
                ldsm_x4(bp, bpBase + p * 2048 + boff);
#pragma unroll
                for (int sub = 0; sub < 2; ++sub)
#pragma unroll
                    for (int mf = 0; mf < 4; ++mf)
                        mma_f16(dP[mf][p * 2 + sub], a[mf], bp + 2 * sub);
            }
        }
    }
}
__device__ __forceinline__ void compute_chunk(uint32_t aBase, uint32_t bBase, const Frag& f,
                                              float (*d)[4][4]) {
#pragma unroll
    for (int ks = 0; ks < 4; ++ks) {
        const uint32_t aoff = (((f.aC0 + 2 * ks) * 16) ^ f.aMask);
        uint32_t a[4][4];
#pragma unroll
        for (int mf = 0; mf < 4; ++mf)
            ldsm_x4(a[mf], aBase + f.aOff + mf * 2048 + aoff);
        const uint32_t boff = f.bRel + (((f.bC0 + 2 * ks) * 16) ^ f.bMask);
#pragma unroll
        for (int p = 0; p < 2; ++p) {
            uint32_t b[4];
            ldsm_x4(b, bBase + p * 2048 + boff);
#pragma unroll
            for (int sub = 0; sub < 2; ++sub)
#pragma unroll
                for (int mf = 0; mf < 4; ++mf)
                    mma_f16(d[mf][p * 2 + sub], a[mf], b + 2 * sub);
        }
    }
}

// ================= persistent fused edge kernel =================
__global__ __launch_bounds__(256, 1) void k_edge(const float* __restrict__ Pb,
                                                 const float* __restrict__ Wb,
                                                 const float* __restrict__ e,
                                                 float* __restrict__ oute) {
    extern __shared__ char smem[];
    const uint32_t sb = smem_u32(smem);
    const int tid = threadIdx.x, lane = tid & 31, warp = tid >> 5;
    const int frow = tid >> 1, fhalf = tid & 1;
    const Frag f = make_frag(warp, lane);
    const int mh = warp >> 2, ws = warp & 3;
    const int r4 = lane >> 2, c2 = (lane & 3) * 2;
    const bool evenlane = ((lane & 1) == 0);

    // resident weights: W (6 chunks) + P (4 chunks)
    for (int l = tid; l < 6144; l += 256)
        cpa16(sb + BW_BASE + (uint32_t)l * 16, (const char*)g_imgW + (size_t)l * 16);
    for (int l = tid; l < 4096; l += 256)
        cpa16(sb + BP_BASE + (uint32_t)l * 16, (const char*)g_imgP + (size_t)l * 16);
    cpa_commit();
    cpa_wait<0>();
    __syncthreads();

    // first tile prologue
    int t = blockIdx.x;
    int fegc, fsrc, ftgt;
    const float* e_row;
    {
        int feg = t * 128 + frow;
        fegc = (feg < NEDGES) ? feg : (NEDGES - 1);
        fsrc = g_src[fegc];
        ftgt = g_tgt[fegc];
        e_row = e + (size_t)fegc * DIM;
        float4 pre[8];
        lda8(e_row, fhalf, pre);
        sta8(smem, A_BASE, frow, fhalf, pre);   // chunk 0 = e[0:64] into A buf0
    }

    for (; t < NT; t += (int)gridDim.x) {
        const int e0 = t * 128;
        const uint32_t* ah[6] = {nullptr, nullptr,
                                 g_h16 + (size_t)fsrc * 64 + fhalf * 16,
                                 g_h16 + (size_t)fsrc * 64 + 32 + fhalf * 16,
                                 g_h16 + (size_t)ftgt * 64 + fhalf * 16,
                                 g_h16 + (size_t)ftgt * 64 + 32 + fhalf * 16};
        float dP[4][4][4], dW[4][4][4];
#pragma unroll
        for (int i = 0; i < 4; ++i)
#pragma unroll
            for (int j = 0; j < 4; ++j)
#pragma unroll
                for (int k = 0; k < 4; ++k) { dP[i][j][k] = 0.f; dW[i][j][k] = 0.f; }

        float4 pre[8];
#pragma unroll 1
        for (int ch = 0; ch < 6; ++ch) {
            if (ch == 0) {
                lda8(e_row + 64, fhalf, pre);           // e[64:128] LDGs in flight
            } else if (ch <= 4) {
                fill_a_async(sb + A_BASE + (uint32_t)(((ch + 1) & 1) * 16384),
                             frow, fhalf, ah[ch + 1]);
                cpa_commit();
            }
            if (ch >= 2) {
                if (ch <= 4) cpa_wait<1>(); else cpa_wait<0>();
            }
            __syncthreads();
            const uint32_t aBase = sb + A_BASE + (uint32_t)((ch & 1) * 16384);
            const int pm = (ch < 2) ? ch + 2 : ((ch < 4) ? ch - 2 : -1);
            compute_chunk_dual(aBase, sb + BW_BASE + (uint32_t)(ch * 16384),
                               sb + BP_BASE + (uint32_t)((pm >= 0 ? pm : 0) * 16384),
                               f, dW, dP, pm >= 0);
            if (ch == 0) sta8(smem, A_BASE + 16384, frow, fhalf, pre);  // e hi -> A buf1
            __syncthreads();
        }

        // prefetch next tile's e[0:64] (LDG latency hidden under epilogue)
        const int tn = t + (int)gridDim.x;
        int fegc_n = 0, fsrc_n = 0, ftgt_n = 0;
        const float* e_row_n = nullptr;
        if (tn < NT) {
            int feg = tn * 128 + frow;
            fegc_n = (feg < NEDGES) ? feg : (NEDGES - 1);
            fsrc_n = g_src[fegc_n];
            ftgt_n = g_tgt[fegc_n];
            e_row_n = e + (size_t)fegc_n * DIM;
            lda8(e_row_n, fhalf, pre);
        }

        // epilogue
#pragma unroll
        for (int mf = 0; mf < 4; ++mf) {
#pragma unroll
            for (int half = 0; half < 2; ++half) {
                const int eg = e0 + mh * 64 + mf * 16 + r4 + half * 8;
                const bool valid = eg < NEDGES;
                const int egc = valid ? eg : (NEDGES - 1);
                float* arow = g_agg + (size_t)__ldg(&g_tgt[egc]) * DIM;
                float* orow = oute + (size_t)egc * DIM;
#pragma unroll
                for (int nfl = 0; nfl < 4; ++nfl) {
                    const int col = ws * 32 + nfl * 8 + c2;
                    float2 bP = __ldg((const float2*)(Pb + col));
                    float2 bW = __ldg((const float2*)(Wb + col));
                    float2 vP, vW;
                    vP.x = fmaxf(dP[mf][nfl][half * 2 + 0] + bP.x, 0.f);
                    vP.y = fmaxf(dP[mf][nfl][half * 2 + 1] + bP.y, 0.f);
                    vW.x = fmaxf(dW[mf][nfl][half * 2 + 0] + bW.x, 0.f);
                    vW.y = fmaxf(dW[mf][nfl][half * 2 + 1] + bW.y, 0.f);
                    float pPx = __shfl_xor_sync(0xffffffffu, vP.x, 1);
                    float pPy = __shfl_xor_sync(0xffffffffu, vP.y, 1);
                    float pWx = __shfl_xor_sync(0xffffffffu, vW.x, 1);
                    float pWy = __shfl_xor_sync(0xffffffffu, vW.y, 1);
                    if (valid && evenlane) {
                        red_v4(arow + col, vP.x, vP.y, pPx, pPy);
                        *(float4*)(orow + col) = make_float4(vW.x, vW.y, pWx, pWy);
                    }
                }
            }
        }

        if (tn < NT) sta8(smem, A_BASE, frow, fhalf, pre);   // next tile chunk0 -> buf0
        fegc = fegc_n; fsrc = fsrc_n; ftgt = ftgt_n; e_row = e_row_n;
    }
}

// ================= node kernel (compact 64KB layout) =================
__global__ __launch_bounds__(256) void k_node(const float* __restrict__ Qb,
                                              float* __restrict__ outh) {
    extern __shared__ char smem[];
    const uint32_t sb = smem_u32(smem);
    const int tid = threadIdx.x, lane = tid & 31, warp = tid >> 5;
    const int n0 = blockIdx.x * 128;
    const int frow = tid >> 1, fhalf = tid & 1;
    const int fng = n0 + frow;
    const int fnode = (fng < NNODES) ? fng : (NNODES - 1);
    const float finvd = 1.f / fmaxf(g_deg[fnode], 1.f);
    const Frag f = make_frag(warp, lane);

    float d[4][4][4];
#pragma unroll
    for (int i = 0; i < 4; ++i)
#pragma unroll
        for (int j = 0; j < 4; ++j)
#pragma unroll
            for (int k = 0; k < 4; ++k) d[i][j][k] = 0.f;

    const uint32_t* as[2] = {g_h16 + (size_t)fnode * 64 + fhalf * 16,
                             g_h16 + (size_t)fnode * 64 + 32 + fhalf * 16};

    // chunks: 0,1 = h (async); 2,3 = agg*invdeg (register path)
    fill_a_async(sb, frow, fhalf, as[0]);
    fill_b_async(sb + 16384, g_imgQ, 0, tid);
    cpa_commit();
#pragma unroll 1
    for (int ch = 0; ch < 4; ++ch) {
        const uint32_t abase = sb + (uint32_t)((ch & 1) * NBUFSZ);
        if (ch + 1 < 4) {
            const uint32_t nabase = sb + (uint32_t)(((ch + 1) & 1) * NBUFSZ);
            if (ch + 1 < 2) fill_a_async(nabase, frow, fhalf, as[ch + 1]);
            else fill_a_f32(smem, ((ch + 1) & 1) * NBUFSZ, frow, fhalf,
                            g_agg + (size_t)fnode * DIM + (ch + 1 - 2) * 64, finvd);
            fill_b_async(nabase + 16384, g_imgQ, ch + 1, tid);
            cpa_commit();
            cpa_wait<1>();
        } else {
            cpa_wait<0>();
        }
        __syncthreads();
        compute_chunk(abase, abase + 16384, f, d);
        __syncthreads();
    }

    const int mh = warp >> 2, ws = warp & 3;
    const int r4 = lane >> 2, c2 = (lane & 3) * 2;
    const bool evenlane = ((lane & 1) == 0);
#pragma unroll
    for (int mf = 0; mf < 4; ++mf) {
#pragma unroll
        for (int half = 0; half < 2; ++half) {
            const int ng = n0 + mh * 64 + mf * 16 + r4 + half * 8;
            const bool valid = ng < NNODES;
            float* orow = outh + (size_t)(valid ? ng : 0) * DIM;
#pragma unroll
            for (int nfl = 0; nfl < 4; ++nfl) {
                const int col = ws * 32 + nfl * 8 + c2;
                float2 bias = __ldg((const float2*)(Qb + col));
                float2 v;
                v.x = fmaxf(d[mf][nfl][half * 2 + 0] + bias.x, 0.f);
                v.y = fmaxf(d[mf][nfl][half * 2 + 1] + bias.y, 0.f);
                float px = __shfl_xor_sync(0xffffffffu, v.x, 1);
                float py = __shfl_xor_sync(0xffffffffu, v.y, 1);
                if (valid && evenlane)
                    *(float4*)(orow + col) = make_float4(v.x, v.y, px, py);
            }
        }
    }
}

extern "C" void kernel_launch(void* const* d_in, const int* in_sizes, int n_in,
                              void* d_out, int out_size) {
    const float* h    = (const float*)d_in[0];
    const float* e    = (const float*)d_in[1];
    const void*  eidx = d_in[2];
    const float* Pw   = (const float*)d_in[3];
    const float* Pb   = (const float*)d_in[4];
    const float* Qw   = (const float*)d_in[5];
    const float* Qb   = (const float*)d_in[6];
    const float* Ww   = (const float*)d_in[7];
    const float* Wb   = (const float*)d_in[8];

    float* outh = (float*)d_out;
    float* oute = outh + (size_t)NNODES * DIM;

    cudaFuncSetAttribute(k_edge, cudaFuncAttributeMaxDynamicSharedMemorySize, SMEM_EDGE);
    cudaFuncSetAttribute(k_node, cudaFuncAttributeMaxDynamicSharedMemorySize, SMEM_NODE);

    const int dblocks = (NEDGES + 255) / 256;
    const int ng = (NNODES + 127) / 128;   // 782

    detect_idx<<<1, 32>>>(eidx);
    decode_idx<<<dblocks, 256>>>(eidx);
    count_deg<<<dblocks, 256>>>();
    prep_h<<<(NNODES * 32 + 255) / 256, 256>>>(h);
    prep_w_all<<<224, 256>>>(Pw, Qw, Ww);
    k_edge<<<148, 256, SMEM_EDGE>>>(Pb, Wb, e, oute);
    k_node<<<ng, 256, SMEM_NODE>>>(Qb, outh);
}

// round 12
// speedup vs baseline: 2.2499x; 1.0001x over previous
#include <cuda_runtime.h>
#include <cuda_fp16.h>
#include <cstdint>

#define NNODES 100000
#define NEDGES 625000
#define DIM 128
#define NT 4883           // edge tiles of 128

// ---- k_edge smem: resident W chunks 0,1 + P chunks 2,3 + double-buffered A ----
#define EW_BASE 0         // 32KB
#define EP_BASE 32768     // 32KB
#define EA_BASE 65536     // 2 x 16KB
#define SMEM_EDGE 98304
// ---- k_pre / k_node: per-buffer A(16K)+B(16K), double-buffered ----
#define NBUFSZ 32768
#define SMEM_NODE 65536

// ---- device scratch ----
__device__ float g_agg[(size_t)NNODES * DIM];
__device__ float g_deg[NNODES];
__device__ int g_src[NEDGES];
__device__ int g_tgt[NEDGES];
__device__ int g_is64;
__device__ uint32_t g_h16[(size_t)NNODES * 64];   // fp16x2-packed h rows
__device__ uint32_t g_Hp[(size_t)NNODES * 64];    // fp16x2 h@P[0:128]
__device__ uint32_t g_Hw1[(size_t)NNODES * 64];   // fp16x2 h@W[128:256]
__device__ uint32_t g_Hw2[(size_t)NNODES * 64];   // fp16x2 h@W[256:384]
__device__ uint32_t g_imgP[4 * 4096];             // swizzled fp16 weight images
__device__ uint32_t g_imgQ[4 * 4096];
__device__ uint32_t g_imgW[6 * 4096];

// ================= helpers =================
__device__ __forceinline__ uint32_t smem_u32(const void* p) {
    uint32_t a;
    asm("{ .reg .u64 t; cvta.to.shared.u64 t, %1; cvt.u32.u64 %0, t; }" : "=r"(a) : "l"(p));
    return a;
}
__device__ __forceinline__ uint32_t cvt_f16x2(float x, float y) {
    uint32_t r;
    asm("cvt.rn.f16x2.f32 %0, %2, %1;" : "=r"(r) : "f"(x), "f"(y));
    return r;
}
__device__ __forceinline__ void ldsm_x4(uint32_t* r, uint32_t addr) {
    asm volatile("ldmatrix.sync.aligned.m8n8.x4.shared.b16 {%0,%1,%2,%3}, [%4];"
                 : "=r"(r[0]), "=r"(r[1]), "=r"(r[2]), "=r"(r[3]) : "r"(addr));
}
__device__ __forceinline__ void mma_f16(float* d, const uint32_t* a, const uint32_t* b) {
    asm volatile(
        "mma.sync.aligned.m16n8k16.row.col.f32.f16.f16.f32 "
        "{%0,%1,%2,%3}, {%4,%5,%6,%7}, {%8,%9}, {%0,%1,%2,%3};"
        : "+f"(d[0]), "+f"(d[1]), "+f"(d[2]), "+f"(d[3])
        : "r"(a[0]), "r"(a[1]), "r"(a[2]), "r"(a[3]), "r"(b[0]), "r"(b[1]));
}
__device__ __forceinline__ void cpa16(uint32_t dst, const void* src) {
    asm volatile("cp.async.cg.shared.global [%0], [%1], 16;" :: "r"(dst), "l"(src));
}
__device__ __forceinline__ void cpa_commit() {
    asm volatile("cp.async.commit_group;" ::: "memory");
}
template <int N>
__device__ __forceinline__ void cpa_wait() {
    asm volatile("cp.async.wait_group %0;" :: "n"(N) : "memory");
}
__device__ __forceinline__ void red_v4(float* ptr, float a, float b, float c, float d) {
    asm volatile("red.global.v4.f32.add [%0], {%1, %2, %3, %4};"
                 :: "l"(ptr), "f"(a), "f"(b), "f"(c), "f"(d) : "memory");
}

// ================= prep kernels =================
__global__ void detect_idx(const void* ei) {
    if (threadIdx.x == 0 && blockIdx.x == 0) {
        const unsigned long long* p = (const unsigned long long*)ei;
        int is64 = 1;
        for (int i = 0; i < 64; ++i)
            if (p[i] >= (unsigned long long)NNODES) { is64 = 0; break; }
        g_is64 = is64;
    }
}
__global__ void decode_idx(const void* ei) {
    int i = blockIdx.x * blockDim.x + threadIdx.x;
    size_t stride = (size_t)gridDim.x * blockDim.x;
    for (size_t j = i; j < (size_t)NNODES * DIM; j += stride) g_agg[j] = 0.f;
    for (size_t j = i; j < NNODES; j += stride) g_deg[j] = 0.f;
    if (i < NEDGES) {
        long long s, t;
        if (g_is64) { s = ((const long long*)ei)[i]; t = ((const long long*)ei)[NEDGES + i]; }
        else        { s = ((const int*)ei)[i];       t = ((const int*)ei)[NEDGES + i]; }
        if (s < 0) s = 0; if (s >= NNODES) s = NNODES - 1;
        if (t < 0) t = 0; if (t >= NNODES) t = NNODES - 1;
        g_src[i] = (int)s; g_tgt[i] = (int)t;
    }
}
__global__ void count_deg() {
    int i = blockIdx.x * blockDim.x + threadIdx.x;
    if (i < NEDGES) atomicAdd(&g_deg[g_tgt[i]], 1.f);
}
__global__ void prep_h(const float* __restrict__ h) {
    size_t id = (size_t)blockIdx.x * blockDim.x + threadIdx.x;
    if (id >= (size_t)NNODES * 32) return;
    float4 v = ((const float4*)h)[id];
    ((uint2*)g_h16)[id] = make_uint2(cvt_f16x2(v.x, v.y), cvt_f16x2(v.z, v.w));
}
__global__ void prep_w_all(const float* __restrict__ Pw, const float* __restrict__ Qw,
                           const float* __restrict__ Ww) {
    int id = blockIdx.x * blockDim.x + threadIdx.x;
    if (id >= 14 * 4096) return;
    int chunk = id >> 12, pos = id & 4095;
    const float* src;
    uint32_t* dst;
    int c;
    if (chunk < 4)      { src = Pw; dst = g_imgP; c = chunk; }
    else if (chunk < 8) { src = Qw; dst = g_imgQ; c = chunk - 4; }
    else                { src = Ww; dst = g_imgW; c = chunk - 8; }
    int n = pos >> 5, kp = pos & 31;
    uint32_t off = n * 128 + kp * 4;
    uint32_t swz = off ^ ((off >> 3) & 0x70);
    int k0 = c * 64 + kp * 2;
    float x = src[(size_t)k0 * DIM + n];
    float y = src[(size_t)(k0 + 1) * DIM + n];
    dst[(c << 12) + (swz >> 2)] = cvt_f16x2(x, y);
}

// ================= fills =================
__device__ __forceinline__ void fill_a_async(uint32_t abase, int row, int half,
                                             const uint32_t* src) {
    const uint32_t mask = (uint32_t)((row & 7) << 4);
    const uint32_t rowbase = abase + (uint32_t)(row * 128);
#pragma unroll
    for (int i = 0; i < 4; ++i) {
        uint32_t off = (((uint32_t)((half * 4 + i) * 16)) ^ mask);
        cpa16(rowbase + off, src + i * 4);
    }
}
__device__ __forceinline__ void lda8(const float* src, int half, float4* pre) {
    const float4* s = (const float4*)src + half * 8;
#pragma unroll
    for (int i = 0; i < 8; ++i) pre[i] = s[i];
}
__device__ __forceinline__ void sta8(char* smem, uint32_t bufofs, int row, int half,
                                     const float4* pre) {
    const uint32_t mask = (uint32_t)((row & 7) << 4);
#pragma unroll
    for (int i = 0; i < 4; ++i) {
        uint4 w;
        w.x = cvt_f16x2(pre[2 * i].x, pre[2 * i].y);
        w.y = cvt_f16x2(pre[2 * i].z, pre[2 * i].w);
        w.z = cvt_f16x2(pre[2 * i + 1].x, pre[2 * i + 1].y);
        w.w = cvt_f16x2(pre[2 * i + 1].z, pre[2 * i + 1].w);
        uint32_t off = (uint32_t)(row * 128) + (((uint32_t)((half * 4 + i) * 16)) ^ mask);
        *(uint4*)(smem + bufofs + off) = w;
    }
}
__device__ __forceinline__ void fill_a_f32(char* smem, uint32_t bufofs, int row, int half,
                                           const float* src, float sc) {
    const float4* s = (const float4*)src + half * 8;
    const uint32_t mask = (uint32_t)((row & 7) << 4);
#pragma unroll
    for (int i = 0; i < 4; ++i) {
        float4 a = s[2 * i], b = s[2 * i + 1];
        uint4 w;
        w.x = cvt_f16x2(a.x * sc, a.y * sc);
        w.y = cvt_f16x2(a.z * sc, a.w * sc);
        w.z = cvt_f16x2(b.x * sc, b.y * sc);
        w.w = cvt_f16x2(b.z * sc, b.w * sc);
        uint32_t off = (uint32_t)(row * 128) + (((uint32_t)((half * 4 + i) * 16)) ^ mask);
        *(uint4*)(smem + bufofs + off) = w;
    }
}
__device__ __forceinline__ void fill_b_async(uint32_t bbase, const uint32_t* img, int ch,
                                             int tid) {
    const uint32_t* s = img + ((size_t)ch << 12) + tid * 4;
#pragma unroll
    for (int i = 0; i < 4; ++i)
        cpa16(bbase + (uint32_t)((i * 256 + tid) * 16), s + i * 1024);
}

// ================= compute =================
struct Frag {
    uint32_t aOff, aMask, aC0;
    uint32_t bRel, bMask, bC0;
};
__device__ __forceinline__ Frag make_frag(int warp, int lane) {
    Frag f;
    const int mh = warp >> 2, ws = warp & 3;
    f.aOff = (uint32_t)((mh * 64 + (lane & 15)) * 128);
    f.aMask = (uint32_t)((lane & 7) << 4);
    f.aC0 = (uint32_t)(lane >> 4);
    f.bRel = (uint32_t)(ws * 4096 + (lane & 7) * 128 + ((lane >> 4) & 1) * 1024);
    f.bMask = (uint32_t)((lane & 7) << 4);
    f.bC0 = (uint32_t)((lane >> 3) & 1);
    return f;
}
__device__ __forceinline__ void compute_chunk_dual(uint32_t aBase, uint32_t bwBase,
                                                   uint32_t bpBase, const Frag& f,
                                                   float (*dW)[4][4], float (*dP)[4][4]) {
#pragma unroll
    for (int ks = 0; ks < 4; ++ks) {
        const uint32_t aoff = (((f.aC0 + 2 * ks) * 16) ^ f.aMask);
        uint32_t a[4][4];
#pragma unroll
        for (int mf = 0; mf < 4; ++mf)
            ldsm_x4(a[mf], aBase + f.aOff + mf * 2048 + aoff);
        const uint32_t boff = f.bRel + (((f.bC0 + 2 * ks) * 16) ^ f.bMask);
#pragma unroll
        for (int p = 0; p < 2; ++p) {
            uint32_t b[4];
            ldsm_x4(b, bwBase + p * 2048 + boff);
#pragma unroll
            for (int sub = 0; sub < 2; ++sub)
#pragma unroll
                for (int mf = 0; mf < 4; ++mf)
                    mma_f16(dW[mf][p * 2 + sub], a[mf], b + 2 * sub);
            uint32_t bp[4];
            ldsm_x4(bp, bpBase + p * 2048 + boff);
#pragma unroll
            for (int sub = 0; sub < 2; ++sub)
#pragma unroll
                for (int mf = 0; mf < 4; ++mf)
                    mma_f16(dP[mf][p * 2 + sub], a[mf], bp + 2 * sub);
        }
    }
}
__device__ __forceinline__ void compute_chunk(uint32_t aBase, uint32_t bBase, const Frag& f,
                                              float (*d)[4][4]) {
#pragma unroll
    for (int ks = 0; ks < 4; ++ks) {
        const uint32_t aoff = (((f.aC0 + 2 * ks) * 16) ^ f.aMask);
        uint32_t a[4][4];
#pragma unroll
        for (int mf = 0; mf < 4; ++mf)
            ldsm_x4(a[mf], aBase + f.aOff + mf * 2048 + aoff);
        const uint32_t boff = f.bRel + (((f.bC0 + 2 * ks) * 16) ^ f.bMask);
#pragma unroll
        for (int p = 0; p < 2; ++p) {
            uint32_t b[4];
            ldsm_x4(b, bBase + p * 2048 + boff);
#pragma unroll
            for (int sub = 0; sub < 2; ++sub)
#pragma unroll
                for (int mf = 0; mf < 4; ++mf)
                    mma_f16(d[mf][p * 2 + sub], a[mf], b + 2 * sub);
        }
    }
}

// ================= k_pre: node projections Hp / Hw1 / Hw2 (fp16 out) ==========
__global__ __launch_bounds__(256) void k_pre() {
    extern __shared__ char smem[];
    const uint32_t sb = smem_u32(smem);
    const int tid = threadIdx.x, lane = tid & 31, warp = tid >> 5;
    const int n0 = blockIdx.x * 128;
    const int sel = blockIdx.y;
    const uint32_t* img = (sel == 0) ? g_imgP : g_imgW;
    const int cbase = (sel == 0) ? 0 : ((sel == 1) ? 2 : 4);
    uint32_t* out = (sel == 0) ? g_Hp : ((sel == 1) ? g_Hw1 : g_Hw2);
    const int frow = tid >> 1, fhalf = tid & 1;
    const int fng = n0 + frow;
    const int fnode = (fng < NNODES) ? fng : (NNODES - 1);
    const Frag f = make_frag(warp, lane);

    float d[4][4][4];
#pragma unroll
    for (int i = 0; i < 4; ++i)
#pragma unroll
        for (int j = 0; j < 4; ++j)
#pragma unroll
            for (int k = 0; k < 4; ++k) d[i][j][k] = 0.f;

    const uint32_t* as0 = g_h16 + (size_t)fnode * 64 + fhalf * 16;
    const uint32_t* as1 = g_h16 + (size_t)fnode * 64 + 32 + fhalf * 16;

    fill_a_async(sb, frow, fhalf, as0);
    fill_b_async(sb + 16384, img, cbase, tid);
    cpa_commit();
    fill_a_async(sb + NBUFSZ, frow, fhalf, as1);
    fill_b_async(sb + NBUFSZ + 16384, img, cbase + 1, tid);
    cpa_commit();
    cpa_wait<1>();
    __syncthreads();
    compute_chunk(sb, sb + 16384, f, d);
    cpa_wait<0>();
    __syncthreads();
    compute_chunk(sb + NBUFSZ, sb + NBUFSZ + 16384, f, d);

    const int mh = warp >> 2, ws = warp & 3;
    const int r4 = lane >> 2, li = lane & 3;
#pragma unroll
    for (int mf = 0; mf < 4; ++mf) {
#pragma unroll
        for (int half = 0; half < 2; ++half) {
            const int ng = n0 + mh * 64 + mf * 16 + r4 + half * 8;
            if (ng < NNODES) {
                uint32_t* orow = out + (size_t)ng * 64 + ws * 16 + li;
#pragma unroll
                for (int nfl = 0; nfl < 4; ++nfl)
                    orow[nfl * 4] = cvt_f16x2(d[mf][nfl][half * 2 + 0],
                                              d[mf][nfl][half * 2 + 1]);
            }
        }
    }
}

// ================= persistent fused edge kernel =================
// dP = e @ P[128:256];  msg = relu(dP + Hp[src] + pb)  -> red.v4 into g_agg[tgt]
// dW = e @ W[0:128];    e_new = relu(dW + Hw1[src] + Hw2[tgt] + wb) -> stg.128
__global__ __launch_bounds__(256, 1) void k_edge(const float* __restrict__ Pb,
                                                 const float* __restrict__ Wb,
                                                 const float* __restrict__ e,
                                                 float* __restrict__ oute) {
    extern __shared__ char smem[];
    const uint32_t sb = smem_u32(smem);
    const int tid = threadIdx.x, lane = tid & 31, warp = tid >> 5;
    const int frow = tid >> 1, fhalf = tid & 1;
    const Frag f = make_frag(warp, lane);
    const int mh = warp >> 2, ws = warp & 3;
    const int r4 = lane >> 2, c2 = (lane & 3) * 2, li = lane & 3;
    const bool evenlane = ((lane & 1) == 0);

    // resident weights: W chunks 0,1 ; P chunks 2,3
    for (int l = tid; l < 2048; l += 256)
        cpa16(sb + EW_BASE + (uint32_t)l * 16, (const char*)g_imgW + (size_t)l * 16);
    for (int l = tid; l < 2048; l += 256)
        cpa16(sb + EP_BASE + (uint32_t)l * 16,
              (const char*)(g_imgP + 2 * 4096) + (size_t)l * 16);
    cpa_commit();
    cpa_wait<0>();
    __syncthreads();

    // hoisted biases (tile-invariant)
    float2 bPr[4], bWr[4];
#pragma unroll
    for (int nfl = 0; nfl < 4; ++nfl) {
        const int col = ws * 32 + nfl * 8 + c2;
        bPr[nfl] = __ldg((const float2*)(Pb + col));
        bWr[nfl] = __ldg((const float2*)(Wb + col));
    }

    int t = blockIdx.x;
    int fegc;
    const float* e_row;
    {
        int feg = t * 128 + frow;
        fegc = (feg < NEDGES) ? feg : (NEDGES - 1);
        e_row = e + (size_t)fegc * DIM;
        float4 pre[8];
        lda8(e_row, fhalf, pre);
        sta8(smem, EA_BASE, frow, fhalf, pre);
    }

    for (; t < NT; t += (int)gridDim.x) {
        const int e0 = t * 128;
        float dP[4][4][4], dW[4][4][4];
#pragma unroll
        for (int i = 0; i < 4; ++i)
#pragma unroll
            for (int j = 0; j < 4; ++j)
#pragma unroll
                for (int k = 0; k < 4; ++k) { dP[i][j][k] = 0.f; dW[i][j][k] = 0.f; }

        float4 pre[8];
        lda8(e_row + 64, fhalf, pre);               // e[64:128] LDGs in flight
        __syncthreads();                             // buf0 visible to all
        compute_chunk_dual(sb + EA_BASE, sb + EW_BASE, sb + EP_BASE, f, dW, dP);
        sta8(smem, EA_BASE + 16384, frow, fhalf, pre);
        __syncthreads();
        compute_chunk_dual(sb + EA_BASE + 16384, sb + EW_BASE + 16384,
                           sb + EP_BASE + 16384, f, dW, dP);

        // prefetch next tile's e[0:64]
        const int tn = t + (int)gridDim.x;
        int fegc_n = 0;
        const float* e_row_n = nullptr;
        if (tn < NT) {
            int feg = tn * 128 + frow;
            fegc_n = (feg < NEDGES) ? feg : (NEDGES - 1);
            e_row_n = e + (size_t)fegc_n * DIM;
            lda8(e_row_n, fhalf, pre);
        }

        // epilogue: gather node projections, bias+relu, scatter/store
#pragma unroll
        for (int mf = 0; mf < 4; ++mf) {
#pragma unroll
            for (int half = 0; half < 2; ++half) {
                const int eg = e0 + mh * 64 + mf * 16 + r4 + half * 8;
                const bool valid = eg < NEDGES;
                const int egc = valid ? eg : (NEDGES - 1);
                const int s = __ldg(&g_src[egc]);
                const int tv = __ldg(&g_tgt[egc]);
                const uint32_t* hpR = g_Hp + (size_t)s * 64 + ws * 16 + li;
                const uint32_t* h1R = g_Hw1 + (size_t)s * 64 + ws * 16 + li;
                const uint32_t* h2R = g_Hw2 + (size_t)tv * 64 + ws * 16 + li;
                float* arow = g_agg + (size_t)tv * DIM;
                float* orow = oute + (size_t)egc * DIM;
#pragma unroll
                for (int nfl = 0; nfl < 4; ++nfl) {
                    uint32_t whp = __ldg(hpR + nfl * 4);
                    uint32_t wh1 = __ldg(h1R + nfl * 4);
                    uint32_t wh2 = __ldg(h2R + nfl * 4);
                    float2 hp = __half22float2(*reinterpret_cast<const __half2*>(&whp));
                    float2 h1 = __half22float2(*reinterpret_cast<const __half2*>(&wh1));
                    float2 h2 = __half22float2(*reinterpret_cast<const __half2*>(&wh2));
                    const int col = ws * 32 + nfl * 8 + c2;
                    float2 vP, vW;
                    vP.x = fmaxf(dP[mf][nfl][half * 2 + 0] + hp.x + bPr[nfl].x, 0.f);
                    vP.y = fmaxf(dP[mf][nfl][half * 2 + 1] + hp.y + bPr[nfl].y, 0.f);
                    vW.x = fmaxf(dW[mf][nfl][half * 2 + 0] + h1.x + h2.x + bWr[nfl].x, 0.f);
                    vW.y = fmaxf(dW[mf][nfl][half * 2 + 1] + h1.y + h2.y + bWr[nfl].y, 0.f);
                    float pPx = __shfl_xor_sync(0xffffffffu, vP.x, 1);
                    float pPy = __shfl_xor_sync(0xffffffffu, vP.y, 1);
                    float pWx = __shfl_xor_sync(0xffffffffu, vW.x, 1);
                    float pWy = __shfl_xor_sync(0xffffffffu, vW.y, 1);
                    if (valid && evenlane) {
                        red_v4(arow + col, vP.x, vP.y, pPx, pPy);
                        *(float4*)(orow + col) = make_float4(vW.x, vW.y, pWx, pWy);
                    }
                }
            }
        }

        if (tn < NT) sta8(smem, EA_BASE, frow, fhalf, pre);
        fegc = fegc_n;
        e_row = e_row_n;
    }
}

// ================= node kernel =================
__global__ __launch_bounds__(256) void k_node(const float* __restrict__ Qb,
                                              float* __restrict__ outh) {
    extern __shared__ char smem[];
    const uint32_t sb = smem_u32(smem);
    const int tid = threadIdx.x, lane = tid & 31, warp = tid >> 5;
    const int n0 = blockIdx.x * 128;
    const int frow = tid >> 1, fhalf = tid & 1;
    const int fng = n0 + frow;
    const int fnode = (fng < NNODES) ? fng : (NNODES - 1);
    const float finvd = 1.f / fmaxf(g_deg[fnode], 1.f);
    const Frag f = make_frag(warp, lane);

    float d[4][4][4];
#pragma unroll
    for (int i = 0; i < 4; ++i)
#pragma unroll
        for (int j = 0; j < 4; ++j)
#pragma unroll
            for (int k = 0; k < 4; ++k) d[i][j][k] = 0.f;

    const uint32_t* as[2] = {g_h16 + (size_t)fnode * 64 + fhalf * 16,
                             g_h16 + (size_t)fnode * 64 + 32 + fhalf * 16};

    fill_a_async(sb, frow, fhalf, as[0]);
    fill_b_async(sb + 16384, g_imgQ, 0, tid);
    cpa_commit();
#pragma unroll 1
    for (int ch = 0; ch < 4; ++ch) {
        const uint32_t abase = sb + (uint32_t)((ch & 1) * NBUFSZ);
        if (ch + 1 < 4) {
            const uint32_t nabase = sb + (uint32_t)(((ch + 1) & 1) * NBUFSZ);
            if (ch + 1 < 2) fill_a_async(nabase, frow, fhalf, as[ch + 1]);
            else fill_a_f32(smem, ((ch + 1) & 1) * NBUFSZ, frow, fhalf,
                            g_agg + (size_t)fnode * DIM + (ch + 1 - 2) * 64, finvd);
            fill_b_async(nabase + 16384, g_imgQ, ch + 1, tid);
            cpa_commit();
            cpa_wait<1>();
        } else {
            cpa_wait<0>();
        }
        __syncthreads();
        compute_chunk(abase, abase + 16384, f, d);
        __syncthreads();
    }

    const int mh = warp >> 2, ws = warp & 3;
    const int r4 = lane >> 2, c2 = (lane & 3) * 2;
    const bool evenlane = ((lane & 1) == 0);
#pragma unroll
    for (int mf = 0; mf < 4; ++mf) {
#pragma unroll
        for (int half = 0; half < 2; ++half) {
            const int ng = n0 + mh * 64 + mf * 16 + r4 + half * 8;
            const bool valid = ng < NNODES;
            float* orow = outh + (size_t)(valid ? ng : 0) * DIM;
#pragma unroll
            for (int nfl = 0; nfl < 4; ++nfl) {
                const int col = ws * 32 + nfl * 8 + c2;
                float2 bias = __ldg((const float2*)(Qb + col));
                float2 v;
                v.x = fmaxf(d[mf][nfl][half * 2 + 0] + bias.x, 0.f);
                v.y = fmaxf(d[mf][nfl][half * 2 + 1] + bias.y, 0.f);
                float px = __shfl_xor_sync(0xffffffffu, v.x, 1);
                float py = __shfl_xor_sync(0xffffffffu, v.y, 1);
                if (valid && evenlane)
                    *(float4*)(orow + col) = make_float4(v.x, v.y, px, py);
            }
        }
    }
}

extern "C" void kernel_launch(void* const* d_in, const int* in_sizes, int n_in,
                              void* d_out, int out_size) {
    const float* h    = (const float*)d_in[0];
    const float* e    = (const float*)d_in[1];
    const void*  eidx = d_in[2];
    const float* Pw   = (const float*)d_in[3];
    const float* Pb   = (const float*)d_in[4];
    const float* Qw   = (const float*)d_in[5];
    const float* Qb   = (const float*)d_in[6];
    const float* Ww   = (const float*)d_in[7];
    const float* Wb   = (const float*)d_in[8];

    float* outh = (float*)d_out;
    float* oute = outh + (size_t)NNODES * DIM;

    cudaFuncSetAttribute(k_pre, cudaFuncAttributeMaxDynamicSharedMemorySize, SMEM_NODE);
    cudaFuncSetAttribute(k_edge, cudaFuncAttributeMaxDynamicSharedMemorySize, SMEM_EDGE);
    cudaFuncSetAttribute(k_node, cudaFuncAttributeMaxDynamicSharedMemorySize, SMEM_NODE);

    const int dblocks = (NEDGES + 255) / 256;
    const int ng = (NNODES + 127) / 128;   // 782

    detect_idx<<<1, 32>>>(eidx);
    decode_idx<<<dblocks, 256>>>(eidx);
    count_deg<<<dblocks, 256>>>();
    prep_h<<<(NNODES * 32 + 255) / 256, 256>>>(h);
    prep_w_all<<<224, 256>>>(Pw, Qw, Ww);
    k_pre<<<dim3(ng, 3), 256, SMEM_NODE>>>();
    k_edge<<<148, 256, SMEM_EDGE>>>(Pb, Wb, e, oute);
    k_node<<<ng, 256, SMEM_NODE>>>(Qb, outh);
}